// round 1
// baseline (speedup 1.0000x reference)
#include <cuda_runtime.h>
#include <math.h>

// Problem constants
#define EE   1024
#define TT   2048
#define BBATCH 4
#define HH   16
#define DD   64
#define MROWS (BBATCH * TT)   // 8192

// ---------------------------------------------------------------------------
// Scratch: __device__ globals (allocation-free per harness rules)
// ---------------------------------------------------------------------------
__device__ __align__(256) float g_q[(size_t)MROWS * EE];
__device__ __align__(256) float g_k[(size_t)MROWS * EE];
__device__ __align__(256) float g_v[(size_t)MROWS * EE];
__device__ __align__(256) float g_ctx[(size_t)MROWS * EE];

// ---------------------------------------------------------------------------
// GEMM (NT): C[m,n] = sum_k A[m*K+k] * B[n*K+k]
// 128x128 block tile, BK=16, 256 threads, 8x8 per-thread microtile.
// ---------------------------------------------------------------------------
__global__ __launch_bounds__(256) void gemm_nt(
    const float* __restrict__ A, const float* __restrict__ B,
    float* __restrict__ C, int M, int N, int K)
{
    __shared__ float As[16][128];   // k-major (transposed on store)
    __shared__ float Bs[16][128];

    const int tid = threadIdx.x;
    const int tx  = tid & 15;       // 0..15
    const int ty  = tid >> 4;       // 0..15
    const int loadRow = tid >> 2;       // 0..63
    const int loadCol = (tid & 3) << 2; // 0,4,8,12
    const int mBase = blockIdx.y * 128;
    const int nBase = blockIdx.x * 128;

    float acc[8][8];
    #pragma unroll
    for (int i = 0; i < 8; i++)
        #pragma unroll
        for (int j = 0; j < 8; j++) acc[i][j] = 0.0f;

    for (int k0 = 0; k0 < K; k0 += 16) {
        #pragma unroll
        for (int p = 0; p < 2; p++) {
            int r = loadRow + p * 64;
            float4 a = *(const float4*)&A[(size_t)(mBase + r) * K + k0 + loadCol];
            As[loadCol + 0][r] = a.x; As[loadCol + 1][r] = a.y;
            As[loadCol + 2][r] = a.z; As[loadCol + 3][r] = a.w;
            float4 b = *(const float4*)&B[(size_t)(nBase + r) * K + k0 + loadCol];
            Bs[loadCol + 0][r] = b.x; Bs[loadCol + 1][r] = b.y;
            Bs[loadCol + 2][r] = b.z; Bs[loadCol + 3][r] = b.w;
        }
        __syncthreads();

        #pragma unroll
        for (int kk = 0; kk < 16; kk++) {
            float4 a0 = *(const float4*)&As[kk][ty * 8];
            float4 a1 = *(const float4*)&As[kk][ty * 8 + 4];
            float4 b0 = *(const float4*)&Bs[kk][tx * 8];
            float4 b1 = *(const float4*)&Bs[kk][tx * 8 + 4];
            float ra[8] = {a0.x, a0.y, a0.z, a0.w, a1.x, a1.y, a1.z, a1.w};
            float rb[8] = {b0.x, b0.y, b0.z, b0.w, b1.x, b1.y, b1.z, b1.w};
            #pragma unroll
            for (int i = 0; i < 8; i++)
                #pragma unroll
                for (int j = 0; j < 8; j++)
                    acc[i][j] = fmaf(ra[i], rb[j], acc[i][j]);
        }
        __syncthreads();
    }

    #pragma unroll
    for (int i = 0; i < 8; i++) {
        int row = mBase + ty * 8 + i;
        float4 c0 = make_float4(acc[i][0], acc[i][1], acc[i][2], acc[i][3]);
        float4 c1 = make_float4(acc[i][4], acc[i][5], acc[i][6], acc[i][7]);
        *(float4*)&C[(size_t)row * N + nBase + tx * 8]     = c0;
        *(float4*)&C[(size_t)row * N + nBase + tx * 8 + 4] = c1;
    }
}

// ---------------------------------------------------------------------------
// Row LayerNorm in place. One block per row of 1024 floats, 256 threads.
// ---------------------------------------------------------------------------
__global__ __launch_bounds__(256) void ln_rows(
    float* __restrict__ X, const float* __restrict__ gamma,
    const float* __restrict__ beta)
{
    float* x = X + (size_t)blockIdx.x * EE;
    const int tid = threadIdx.x;

    float4 v = *(const float4*)&x[tid * 4];
    float s  = v.x + v.y + v.z + v.w;
    float sq = v.x * v.x + v.y * v.y + v.z * v.z + v.w * v.w;

    #pragma unroll
    for (int off = 16; off > 0; off >>= 1) {
        s  += __shfl_xor_sync(0xffffffffu, s,  off);
        sq += __shfl_xor_sync(0xffffffffu, sq, off);
    }
    __shared__ float ss[8], sqs[8];
    const int wid = tid >> 5, lane = tid & 31;
    if (lane == 0) { ss[wid] = s; sqs[wid] = sq; }
    __syncthreads();
    float ts = 0.0f, tsq = 0.0f;
    #pragma unroll
    for (int w = 0; w < 8; w++) { ts += ss[w]; tsq += sqs[w]; }

    const float inv_n = 1.0f / (float)EE;
    float mean = ts * inv_n;
    float var  = tsq * inv_n - mean * mean;
    float rstd = rsqrtf(var + 1e-5f);

    float4 g = *(const float4*)&gamma[tid * 4];
    float4 b = *(const float4*)&beta[tid * 4];
    v.x = (v.x - mean) * rstd * g.x + b.x;
    v.y = (v.y - mean) * rstd * g.y + b.y;
    v.z = (v.z - mean) * rstd * g.z + b.z;
    v.w = (v.w - mean) * rstd * g.w + b.w;
    *(float4*)&x[tid * 4] = v;
}

// ---------------------------------------------------------------------------
// Flash attention, fp32. One block = (batch b, head h, 64 q-rows).
// KV tiles of 64 rows, D=64. 256 threads, 4x4 microtiles.
// smem: Qt (d-major), Kt (d-major), Vs (kr-major), Pt (kr-major), stride 68.
// ---------------------------------------------------------------------------
#define FSPAD 68

__device__ __forceinline__ float rowmax16(float v) {
    #pragma unroll
    for (int off = 8; off > 0; off >>= 1)
        v = fmaxf(v, __shfl_xor_sync(0xffffffffu, v, off, 16));
    return v;
}
__device__ __forceinline__ float rowsum16(float v) {
    #pragma unroll
    for (int off = 8; off > 0; off >>= 1)
        v += __shfl_xor_sync(0xffffffffu, v, off, 16);
    return v;
}

__global__ __launch_bounds__(256) void flash64(
    const float* __restrict__ Q, const float* __restrict__ K,
    const float* __restrict__ V, float* __restrict__ O)
{
    extern __shared__ float sm[];
    float* Qt = sm;                  // [64 d][FSPAD] columns = q-row
    float* Kt = Qt + 64 * FSPAD;     // [64 d][FSPAD] columns = k-row
    float* Vs = Kt + 64 * FSPAD;     // [64 kr][FSPAD] columns = d
    float* Pt = Vs + 64 * FSPAD;     // [64 kr][FSPAD] columns = q-row

    const int b  = blockIdx.z;
    const int h  = blockIdx.y;
    const int q0 = blockIdx.x * 64;
    const int tid = threadIdx.x;
    const int tx = tid & 15;         // k-col / d-col group
    const int ty = tid >> 4;         // q-row group
    const size_t headOff = (size_t)h * DD;

    // Load Q tile transposed (d-major)
    {
        const int r = tid >> 4;
        const int c = (tid & 15) * 4;
        #pragma unroll
        for (int p = 0; p < 4; p++) {
            int rr = r + p * 16;
            float4 v = *(const float4*)&Q[((size_t)(b * TT + q0 + rr)) * EE + headOff + c];
            Qt[(c + 0) * FSPAD + rr] = v.x;
            Qt[(c + 1) * FSPAD + rr] = v.y;
            Qt[(c + 2) * FSPAD + rr] = v.z;
            Qt[(c + 3) * FSPAD + rr] = v.w;
        }
    }

    float m_run[4], l_run[4], o[4][4];
    #pragma unroll
    for (int i = 0; i < 4; i++) {
        m_run[i] = -INFINITY; l_run[i] = 0.0f;
        #pragma unroll
        for (int j = 0; j < 4; j++) o[i][j] = 0.0f;
    }

    for (int kv0 = 0; kv0 < TT; kv0 += 64) {
        __syncthreads();   // previous tile's PV reads of Vs/Pt complete
        {
            const int r = tid >> 4;
            const int c = (tid & 15) * 4;
            #pragma unroll
            for (int p = 0; p < 4; p++) {
                int rr = r + p * 16;
                size_t gidx = ((size_t)(b * TT + kv0 + rr)) * EE + headOff + c;
                float4 kvv = *(const float4*)&K[gidx];
                Kt[(c + 0) * FSPAD + rr] = kvv.x;
                Kt[(c + 1) * FSPAD + rr] = kvv.y;
                Kt[(c + 2) * FSPAD + rr] = kvv.z;
                Kt[(c + 3) * FSPAD + rr] = kvv.w;
                float4 vv = *(const float4*)&V[gidx];
                *(float4*)&Vs[rr * FSPAD + c] = vv;
            }
        }
        __syncthreads();

        // S = (Q K^T) * scale   — 4x4 per thread
        float s[4][4];
        #pragma unroll
        for (int i = 0; i < 4; i++)
            #pragma unroll
            for (int j = 0; j < 4; j++) s[i][j] = 0.0f;

        #pragma unroll 8
        for (int d = 0; d < 64; d++) {
            float4 qa = *(const float4*)&Qt[d * FSPAD + ty * 4];
            float4 kb = *(const float4*)&Kt[d * FSPAD + tx * 4];
            float ra[4] = {qa.x, qa.y, qa.z, qa.w};
            float rb[4] = {kb.x, kb.y, kb.z, kb.w};
            #pragma unroll
            for (int i = 0; i < 4; i++)
                #pragma unroll
                for (int j = 0; j < 4; j++)
                    s[i][j] = fmaf(ra[i], rb[j], s[i][j]);
        }

        const float scale = 0.125f;  // 1/sqrt(64)
        #pragma unroll
        for (int i = 0; i < 4; i++) {
            float mt = s[i][0] * scale;
            #pragma unroll
            for (int j = 1; j < 4; j++) mt = fmaxf(mt, s[i][j] * scale);
            mt = rowmax16(mt);
            float mn   = fmaxf(m_run[i], mt);
            float corr = __expf(m_run[i] - mn);
            m_run[i] = mn;
            float rs = 0.0f;
            #pragma unroll
            for (int j = 0; j < 4; j++) {
                float p = __expf(fmaf(s[i][j], scale, -mn));
                s[i][j] = p;
                rs += p;
            }
            rs = rowsum16(rs);
            l_run[i] = l_run[i] * corr + rs;
            #pragma unroll
            for (int j = 0; j < 4; j++) o[i][j] *= corr;
        }

        // Store P transposed (kr-major)
        #pragma unroll
        for (int j = 0; j < 4; j++)
            #pragma unroll
            for (int i = 0; i < 4; i++)
                Pt[(tx * 4 + j) * FSPAD + ty * 4 + i] = s[i][j];
        __syncthreads();

        // O += P V
        #pragma unroll 8
        for (int kr = 0; kr < 64; kr++) {
            float4 pa = *(const float4*)&Pt[kr * FSPAD + ty * 4];
            float4 vb = *(const float4*)&Vs[kr * FSPAD + tx * 4];
            float rp[4] = {pa.x, pa.y, pa.z, pa.w};
            float rv[4] = {vb.x, vb.y, vb.z, vb.w};
            #pragma unroll
            for (int i = 0; i < 4; i++)
                #pragma unroll
                for (int j = 0; j < 4; j++)
                    o[i][j] = fmaf(rp[i], rv[j], o[i][j]);
        }
    }

    #pragma unroll
    for (int i = 0; i < 4; i++) {
        float inv = 1.0f / l_run[i];
        float4 w = make_float4(o[i][0] * inv, o[i][1] * inv,
                               o[i][2] * inv, o[i][3] * inv);
        *(float4*)&O[((size_t)(b * TT + q0 + ty * 4 + i)) * EE + headOff + tx * 4] = w;
    }
}

// ---------------------------------------------------------------------------
// Launch
// ---------------------------------------------------------------------------
extern "C" void kernel_launch(void* const* d_in, const int* in_sizes, int n_in,
                              void* d_out, int out_size)
{
    const float* xq  = (const float*)d_in[0];
    const float* xkv = (const float*)d_in[1];
    const float* Wq  = (const float*)d_in[2];
    const float* Wk  = (const float*)d_in[3];
    const float* Wv  = (const float*)d_in[4];
    const float* Wo  = (const float*)d_in[5];
    const float* qg  = (const float*)d_in[6];
    const float* qb  = (const float*)d_in[7];
    const float* kg  = (const float*)d_in[8];
    const float* kb  = (const float*)d_in[9];

    float *q, *k, *v, *ctx;
    cudaGetSymbolAddress((void**)&q,   g_q);
    cudaGetSymbolAddress((void**)&k,   g_k);
    cudaGetSymbolAddress((void**)&v,   g_v);
    cudaGetSymbolAddress((void**)&ctx, g_ctx);

    dim3 gemmGrid(EE / 128, MROWS / 128);

    gemm_nt<<<gemmGrid, 256>>>(xq,  Wq, q, MROWS, EE, EE);
    gemm_nt<<<gemmGrid, 256>>>(xkv, Wk, k, MROWS, EE, EE);
    gemm_nt<<<gemmGrid, 256>>>(xkv, Wv, v, MROWS, EE, EE);

    ln_rows<<<MROWS, 256>>>(q, qg, qb);
    ln_rows<<<MROWS, 256>>>(k, kg, kb);

    int smemBytes = 4 * 64 * FSPAD * (int)sizeof(float);  // 69632
    cudaFuncSetAttribute((const void*)flash64,
                         cudaFuncAttributeMaxDynamicSharedMemorySize, smemBytes);
    flash64<<<dim3(TT / 64, HH, BBATCH), 256, smemBytes>>>(q, k, v, ctx);

    gemm_nt<<<gemmGrid, 256>>>(ctx, Wo, (float*)d_out, MROWS, EE, EE);
}

// round 3
// speedup vs baseline: 1.3405x; 1.3405x over previous
#include <cuda_runtime.h>
#include <cuda_bf16.h>
#include <math.h>

// Problem constants
#define EE   1024
#define TT   2048
#define BBATCH 4
#define HH   16
#define DD   64
#define MROWS (BBATCH * TT)   // 8192

// ---------------------------------------------------------------------------
// Scratch: __device__ globals (allocation-free per harness rules)
// ---------------------------------------------------------------------------
__device__ __align__(256) float g_q[(size_t)MROWS * EE];
__device__ __align__(256) float g_k[(size_t)MROWS * EE];
__device__ __align__(256) float g_v[(size_t)MROWS * EE];
__device__ __align__(256) float g_ctx[(size_t)MROWS * EE];
__device__ __align__(256) __nv_bfloat16 g_ahi[(size_t)MROWS * EE];
__device__ __align__(256) __nv_bfloat16 g_alo[(size_t)MROWS * EE];
__device__ __align__(256) __nv_bfloat16 g_whi[4][(size_t)EE * EE];
__device__ __align__(256) __nv_bfloat16 g_wlo[4][(size_t)EE * EE];

// ---------------------------------------------------------------------------
// Split fp32 -> (hi, lo) bf16.  x ~= hi + lo with ~16-bit effective mantissa.
// ---------------------------------------------------------------------------
__global__ __launch_bounds__(256) void split_bf16(
    const float* __restrict__ x,
    __nv_bfloat16* __restrict__ hi, __nv_bfloat16* __restrict__ lo, int n4)
{
    int i = blockIdx.x * 256 + threadIdx.x;
    if (i >= n4) return;
    float4 v = ((const float4*)x)[i];
    union { __nv_bfloat16 b[4]; uint2 u; } H, L;
    H.b[0] = __float2bfloat16(v.x); L.b[0] = __float2bfloat16(v.x - __bfloat162float(H.b[0]));
    H.b[1] = __float2bfloat16(v.y); L.b[1] = __float2bfloat16(v.y - __bfloat162float(H.b[1]));
    H.b[2] = __float2bfloat16(v.z); L.b[2] = __float2bfloat16(v.z - __bfloat162float(H.b[2]));
    H.b[3] = __float2bfloat16(v.w); L.b[3] = __float2bfloat16(v.w - __bfloat162float(H.b[3]));
    ((uint2*)hi)[i] = H.u;
    ((uint2*)lo)[i] = L.u;
}

// ---------------------------------------------------------------------------
// Tensor-core NT GEMM with 3-term bf16 split:
//   C = Ahi*Bhi + Ahi*Blo + Alo*Bhi   (fp32 accumulate)
// A: [M,K] row-major bf16 (hi/lo), B: [N,K] row-major bf16 (hi/lo), C: [M,N] f32
// Block tile 128x128x32, 8 warps (warp tile 32x64), double-buffered smem.
// ---------------------------------------------------------------------------
#define BM 128
#define BN 128
#define BK 32
#define LDT 40                 // padded smem row stride (bf16 units)
#define TILE_E (BM * LDT)      // one operand tile, bf16 elems
#define STAGE_E (4 * TILE_E)   // Ah, Al, Bh, Bl

__device__ __forceinline__ void ldsm_x4(unsigned* r, unsigned addr) {
    asm volatile("ldmatrix.sync.aligned.m8n8.x4.shared.b16 {%0,%1,%2,%3}, [%4];\n"
                 : "=r"(r[0]), "=r"(r[1]), "=r"(r[2]), "=r"(r[3]) : "r"(addr));
}
__device__ __forceinline__ void mma16816(float* c, const unsigned* a, const unsigned* b) {
    asm volatile(
        "mma.sync.aligned.m16n8k16.row.col.f32.bf16.bf16.f32 "
        "{%0,%1,%2,%3}, {%4,%5,%6,%7}, {%8,%9}, {%0,%1,%2,%3};\n"
        : "+f"(c[0]), "+f"(c[1]), "+f"(c[2]), "+f"(c[3])
        : "r"(a[0]), "r"(a[1]), "r"(a[2]), "r"(a[3]), "r"(b[0]), "r"(b[1]));
}

__global__ __launch_bounds__(256) void gemm_bf16x3(
    const __nv_bfloat16* __restrict__ Ah, const __nv_bfloat16* __restrict__ Al,
    const __nv_bfloat16* __restrict__ Bh, const __nv_bfloat16* __restrict__ Bl,
    float* __restrict__ C, int M, int N, int K)
{
    extern __shared__ __nv_bfloat16 smem[];
    const int tid  = threadIdx.x;
    const int wid  = tid >> 5;
    const int lane = tid & 31;
    const int warpM = wid & 3;        // 0..3  (m offset 32 each)
    const int warpN = wid >> 2;       // 0..1  (n offset 64 each)
    const int mBase = blockIdx.y * BM;
    const int nBase = blockIdx.x * BN;

    const unsigned sbase = (unsigned)__cvta_generic_to_shared(smem);

    // loader geometry: thread covers 2 rows (stride 64), 16B per row per tile
    const int lrow = tid >> 2;            // 0..63
    const int lcol = (tid & 3) * 8;       // 0,8,16,24 (bf16 units)

    float acc[2][8][4];
    #pragma unroll
    for (int t = 0; t < 2; t++)
        #pragma unroll
        for (int j = 0; j < 8; j++)
            #pragma unroll
            for (int e = 0; e < 4; e++) acc[t][j][e] = 0.0f;

    const int nsteps = K / BK;   // 32

    // ---- load stage 0 directly to smem ----
    {
        #pragma unroll
        for (int c = 0; c < 2; c++) {
            int row = lrow + c * 64;
            uint4 va = *(const uint4*)&Ah[(size_t)(mBase + row) * K + lcol];
            uint4 vb = *(const uint4*)&Al[(size_t)(mBase + row) * K + lcol];
            uint4 vc = *(const uint4*)&Bh[(size_t)(nBase + row) * K + lcol];
            uint4 vd = *(const uint4*)&Bl[(size_t)(nBase + row) * K + lcol];
            int so = row * LDT + lcol;
            *(uint4*)&smem[0 * TILE_E + so] = va;
            *(uint4*)&smem[1 * TILE_E + so] = vb;
            *(uint4*)&smem[2 * TILE_E + so] = vc;
            *(uint4*)&smem[3 * TILE_E + so] = vd;
        }
    }
    __syncthreads();

    uint4 rg[8];
    for (int step = 0; step < nsteps; step++) {
        const int cur = step & 1;

        // prefetch next stage into registers
        if (step + 1 < nsteps) {
            const int k0 = (step + 1) * BK;
            #pragma unroll
            for (int c = 0; c < 2; c++) {
                int row = lrow + c * 64;
                rg[c * 4 + 0] = *(const uint4*)&Ah[(size_t)(mBase + row) * K + k0 + lcol];
                rg[c * 4 + 1] = *(const uint4*)&Al[(size_t)(mBase + row) * K + k0 + lcol];
                rg[c * 4 + 2] = *(const uint4*)&Bh[(size_t)(nBase + row) * K + k0 + lcol];
                rg[c * 4 + 3] = *(const uint4*)&Bl[(size_t)(nBase + row) * K + k0 + lcol];
            }
        }

        // compute current stage
        const unsigned aBaseH = sbase + (cur * STAGE_E + 0 * TILE_E) * 2;
        const unsigned aBaseL = sbase + (cur * STAGE_E + 1 * TILE_E) * 2;
        const unsigned bBaseH = sbase + (cur * STAGE_E + 2 * TILE_E) * 2;
        const unsigned bBaseL = sbase + (cur * STAGE_E + 3 * TILE_E) * 2;

        #pragma unroll
        for (int kk = 0; kk < BK; kk += 16) {
            unsigned fAh[2][4], fAl[2][4];
            const int aCol = kk + ((lane >> 4) << 3);
            #pragma unroll
            for (int t = 0; t < 2; t++) {
                int aRow = warpM * 32 + t * 16 + (lane & 15);
                unsigned off = (unsigned)(aRow * LDT + aCol) * 2;
                ldsm_x4(fAh[t], aBaseH + off);
                ldsm_x4(fAl[t], aBaseL + off);
            }
            #pragma unroll
            for (int np = 0; np < 4; np++) {
                const int n0  = warpN * 64 + np * 16;
                const int grp = lane >> 3, r = lane & 7;
                const int bRow = n0 + ((grp & 2) << 2) + r;
                const int bCol = kk + ((grp & 1) << 3);
                unsigned boff = (unsigned)(bRow * LDT + bCol) * 2;
                unsigned fBh[4], fBl[4];
                ldsm_x4(fBh, bBaseH + boff);
                ldsm_x4(fBl, bBaseL + boff);
                #pragma unroll
                for (int t = 0; t < 2; t++) {
                    mma16816(acc[t][np * 2 + 0], fAh[t], fBh + 0);
                    mma16816(acc[t][np * 2 + 1], fAh[t], fBh + 2);
                    mma16816(acc[t][np * 2 + 0], fAh[t], fBl + 0);
                    mma16816(acc[t][np * 2 + 1], fAh[t], fBl + 2);
                    mma16816(acc[t][np * 2 + 0], fAl[t], fBh + 0);
                    mma16816(acc[t][np * 2 + 1], fAl[t], fBh + 2);
                }
            }
        }

        // store prefetched stage
        if (step + 1 < nsteps) {
            const int nxt = 1 - cur;
            #pragma unroll
            for (int c = 0; c < 2; c++) {
                int row = lrow + c * 64;
                int so = nxt * STAGE_E + row * LDT + lcol;
                *(uint4*)&smem[so + 0 * TILE_E] = rg[c * 4 + 0];
                *(uint4*)&smem[so + 1 * TILE_E] = rg[c * 4 + 1];
                *(uint4*)&smem[so + 2 * TILE_E] = rg[c * 4 + 2];
                *(uint4*)&smem[so + 3 * TILE_E] = rg[c * 4 + 3];
            }
            __syncthreads();
        }
    }

    // epilogue
    #pragma unroll
    for (int t = 0; t < 2; t++) {
        int row = mBase + warpM * 32 + t * 16 + (lane >> 2);
        #pragma unroll
        for (int j = 0; j < 8; j++) {
            int col = nBase + warpN * 64 + j * 8 + (lane & 3) * 2;
            float2 lo2 = make_float2(acc[t][j][0], acc[t][j][1]);
            float2 hi2 = make_float2(acc[t][j][2], acc[t][j][3]);
            *(float2*)&C[(size_t)row * N + col]       = lo2;
            *(float2*)&C[(size_t)(row + 8) * N + col] = hi2;
        }
    }
}

// ---------------------------------------------------------------------------
// Row LayerNorm in place. One block per row of 1024 floats, 256 threads.
// ---------------------------------------------------------------------------
__global__ __launch_bounds__(256) void ln_rows(
    float* __restrict__ X, const float* __restrict__ gamma,
    const float* __restrict__ beta)
{
    float* x = X + (size_t)blockIdx.x * EE;
    const int tid = threadIdx.x;

    float4 v = *(const float4*)&x[tid * 4];
    float s  = v.x + v.y + v.z + v.w;
    float sq = v.x * v.x + v.y * v.y + v.z * v.z + v.w * v.w;

    #pragma unroll
    for (int off = 16; off > 0; off >>= 1) {
        s  += __shfl_xor_sync(0xffffffffu, s,  off);
        sq += __shfl_xor_sync(0xffffffffu, sq, off);
    }
    __shared__ float ss[8], sqs[8];
    const int wid = tid >> 5, lane = tid & 31;
    if (lane == 0) { ss[wid] = s; sqs[wid] = sq; }
    __syncthreads();
    float ts = 0.0f, tsq = 0.0f;
    #pragma unroll
    for (int w = 0; w < 8; w++) { ts += ss[w]; tsq += sqs[w]; }

    const float inv_n = 1.0f / (float)EE;
    float mean = ts * inv_n;
    float var  = tsq * inv_n - mean * mean;
    float rstd = rsqrtf(var + 1e-5f);

    float4 g = *(const float4*)&gamma[tid * 4];
    float4 b = *(const float4*)&beta[tid * 4];
    v.x = (v.x - mean) * rstd * g.x + b.x;
    v.y = (v.y - mean) * rstd * g.y + b.y;
    v.z = (v.z - mean) * rstd * g.z + b.z;
    v.w = (v.w - mean) * rstd * g.w + b.w;
    *(float4*)&x[tid * 4] = v;
}

// ---------------------------------------------------------------------------
// Flash attention, fp32 (unchanged from R1 — known correct).
// ---------------------------------------------------------------------------
#define FSPAD 68

__device__ __forceinline__ float rowmax16(float v) {
    #pragma unroll
    for (int off = 8; off > 0; off >>= 1)
        v = fmaxf(v, __shfl_xor_sync(0xffffffffu, v, off, 16));
    return v;
}
__device__ __forceinline__ float rowsum16(float v) {
    #pragma unroll
    for (int off = 8; off > 0; off >>= 1)
        v += __shfl_xor_sync(0xffffffffu, v, off, 16);
    return v;
}

__global__ __launch_bounds__(256) void flash64(
    const float* __restrict__ Q, const float* __restrict__ K,
    const float* __restrict__ V, float* __restrict__ O)
{
    extern __shared__ float sm[];
    float* Qt = sm;
    float* Kt = Qt + 64 * FSPAD;
    float* Vs = Kt + 64 * FSPAD;
    float* Pt = Vs + 64 * FSPAD;

    const int b  = blockIdx.z;
    const int h  = blockIdx.y;
    const int q0 = blockIdx.x * 64;
    const int tid = threadIdx.x;
    const int tx = tid & 15;
    const int ty = tid >> 4;
    const size_t headOff = (size_t)h * DD;

    {
        const int r = tid >> 4;
        const int c = (tid & 15) * 4;
        #pragma unroll
        for (int p = 0; p < 4; p++) {
            int rr = r + p * 16;
            float4 v = *(const float4*)&Q[((size_t)(b * TT + q0 + rr)) * EE + headOff + c];
            Qt[(c + 0) * FSPAD + rr] = v.x;
            Qt[(c + 1) * FSPAD + rr] = v.y;
            Qt[(c + 2) * FSPAD + rr] = v.z;
            Qt[(c + 3) * FSPAD + rr] = v.w;
        }
    }

    float m_run[4], l_run[4], o[4][4];
    #pragma unroll
    for (int i = 0; i < 4; i++) {
        m_run[i] = -INFINITY; l_run[i] = 0.0f;
        #pragma unroll
        for (int j = 0; j < 4; j++) o[i][j] = 0.0f;
    }

    for (int kv0 = 0; kv0 < TT; kv0 += 64) {
        __syncthreads();
        {
            const int r = tid >> 4;
            const int c = (tid & 15) * 4;
            #pragma unroll
            for (int p = 0; p < 4; p++) {
                int rr = r + p * 16;
                size_t gidx = ((size_t)(b * TT + kv0 + rr)) * EE + headOff + c;
                float4 kvv = *(const float4*)&K[gidx];
                Kt[(c + 0) * FSPAD + rr] = kvv.x;
                Kt[(c + 1) * FSPAD + rr] = kvv.y;
                Kt[(c + 2) * FSPAD + rr] = kvv.z;
                Kt[(c + 3) * FSPAD + rr] = kvv.w;
                float4 vv = *(const float4*)&V[gidx];
                *(float4*)&Vs[rr * FSPAD + c] = vv;
            }
        }
        __syncthreads();

        float s[4][4];
        #pragma unroll
        for (int i = 0; i < 4; i++)
            #pragma unroll
            for (int j = 0; j < 4; j++) s[i][j] = 0.0f;

        #pragma unroll 8
        for (int d = 0; d < 64; d++) {
            float4 qa = *(const float4*)&Qt[d * FSPAD + ty * 4];
            float4 kb = *(const float4*)&Kt[d * FSPAD + tx * 4];
            float ra[4] = {qa.x, qa.y, qa.z, qa.w};
            float rb[4] = {kb.x, kb.y, kb.z, kb.w};
            #pragma unroll
            for (int i = 0; i < 4; i++)
                #pragma unroll
                for (int j = 0; j < 4; j++)
                    s[i][j] = fmaf(ra[i], rb[j], s[i][j]);
        }

        const float scale = 0.125f;
        #pragma unroll
        for (int i = 0; i < 4; i++) {
            float mt = s[i][0] * scale;
            #pragma unroll
            for (int j = 1; j < 4; j++) mt = fmaxf(mt, s[i][j] * scale);
            mt = rowmax16(mt);
            float mn   = fmaxf(m_run[i], mt);
            float corr = __expf(m_run[i] - mn);
            m_run[i] = mn;
            float rs = 0.0f;
            #pragma unroll
            for (int j = 0; j < 4; j++) {
                float p = __expf(fmaf(s[i][j], scale, -mn));
                s[i][j] = p;
                rs += p;
            }
            rs = rowsum16(rs);
            l_run[i] = l_run[i] * corr + rs;
            #pragma unroll
            for (int j = 0; j < 4; j++) o[i][j] *= corr;
        }

        #pragma unroll
        for (int j = 0; j < 4; j++)
            #pragma unroll
            for (int i = 0; i < 4; i++)
                Pt[(tx * 4 + j) * FSPAD + ty * 4 + i] = s[i][j];
        __syncthreads();

        #pragma unroll 8
        for (int kr = 0; kr < 64; kr++) {
            float4 pa = *(const float4*)&Pt[kr * FSPAD + ty * 4];
            float4 vb = *(const float4*)&Vs[kr * FSPAD + tx * 4];
            float rp[4] = {pa.x, pa.y, pa.z, pa.w};
            float rv[4] = {vb.x, vb.y, vb.z, vb.w};
            #pragma unroll
            for (int i = 0; i < 4; i++)
                #pragma unroll
                for (int j = 0; j < 4; j++)
                    o[i][j] = fmaf(rp[i], rv[j], o[i][j]);
        }
    }

    #pragma unroll
    for (int i = 0; i < 4; i++) {
        float inv = 1.0f / l_run[i];
        float4 w = make_float4(o[i][0] * inv, o[i][1] * inv,
                               o[i][2] * inv, o[i][3] * inv);
        *(float4*)&O[((size_t)(b * TT + q0 + ty * 4 + i)) * EE + headOff + tx * 4] = w;
    }
}

// ---------------------------------------------------------------------------
// Launch
// ---------------------------------------------------------------------------
extern "C" void kernel_launch(void* const* d_in, const int* in_sizes, int n_in,
                              void* d_out, int out_size)
{
    const float* xq  = (const float*)d_in[0];
    const float* xkv = (const float*)d_in[1];
    const float* W[4] = { (const float*)d_in[2], (const float*)d_in[3],
                          (const float*)d_in[4], (const float*)d_in[5] };
    const float* qg  = (const float*)d_in[6];
    const float* qb  = (const float*)d_in[7];
    const float* kg  = (const float*)d_in[8];
    const float* kb  = (const float*)d_in[9];

    float *q, *k, *v, *ctx;
    __nv_bfloat16 *ahi, *alo, *whi, *wlo;
    cudaGetSymbolAddress((void**)&q,   g_q);
    cudaGetSymbolAddress((void**)&k,   g_k);
    cudaGetSymbolAddress((void**)&v,   g_v);
    cudaGetSymbolAddress((void**)&ctx, g_ctx);
    cudaGetSymbolAddress((void**)&ahi, g_ahi);
    cudaGetSymbolAddress((void**)&alo, g_alo);
    cudaGetSymbolAddress((void**)&whi, g_whi);
    cudaGetSymbolAddress((void**)&wlo, g_wlo);

    const size_t wsz = (size_t)EE * EE;
    const int nW4 = (int)(wsz / 4);
    const int nA4 = (int)((size_t)MROWS * EE / 4);

    int smemGemm = 2 * STAGE_E * 2;  // 81920 bytes
    int smemFlash = 4 * 64 * FSPAD * (int)sizeof(float);
    cudaFuncSetAttribute((const void*)gemm_bf16x3,
                         cudaFuncAttributeMaxDynamicSharedMemorySize, smemGemm);
    cudaFuncSetAttribute((const void*)flash64,
                         cudaFuncAttributeMaxDynamicSharedMemorySize, smemFlash);

    // weight splits (deterministic, recomputed every launch)
    for (int i = 0; i < 4; i++)
        split_bf16<<<(nW4 + 255) / 256, 256>>>(W[i], whi + i * wsz, wlo + i * wsz, nW4);

    dim3 gGrid(EE / BN, MROWS / BM);   // (8, 64)

    // Q projection
    split_bf16<<<(nA4 + 255) / 256, 256>>>(xq, ahi, alo, nA4);
    gemm_bf16x3<<<gGrid, 256, smemGemm>>>(ahi, alo, whi + 0 * wsz, wlo + 0 * wsz,
                                          q, MROWS, EE, EE);
    // K, V projections (share xkv split)
    split_bf16<<<(nA4 + 255) / 256, 256>>>(xkv, ahi, alo, nA4);
    gemm_bf16x3<<<gGrid, 256, smemGemm>>>(ahi, alo, whi + 1 * wsz, wlo + 1 * wsz,
                                          k, MROWS, EE, EE);
    gemm_bf16x3<<<gGrid, 256, smemGemm>>>(ahi, alo, whi + 2 * wsz, wlo + 2 * wsz,
                                          v, MROWS, EE, EE);

    ln_rows<<<MROWS, 256>>>(q, qg, qb);
    ln_rows<<<MROWS, 256>>>(k, kg, kb);

    flash64<<<dim3(TT / 64, HH, BBATCH), 256, smemFlash>>>(q, k, v, ctx);

    // Output projection
    split_bf16<<<(nA4 + 255) / 256, 256>>>(ctx, ahi, alo, nA4);
    gemm_bf16x3<<<gGrid, 256, smemGemm>>>(ahi, alo, whi + 3 * wsz, wlo + 3 * wsz,
                                          (float*)d_out, MROWS, EE, EE);
}

// round 4
// speedup vs baseline: 2.2264x; 1.6609x over previous
#include <cuda_runtime.h>
#include <cuda_bf16.h>
#include <math.h>

// Problem constants
#define EE   1024
#define TT   2048
#define BBATCH 4
#define HH   16
#define DD   64
#define MROWS (BBATCH * TT)   // 8192

// ---------------------------------------------------------------------------
// Scratch: __device__ globals (allocation-free per harness rules)
// ---------------------------------------------------------------------------
__device__ __align__(256) float g_q[(size_t)MROWS * EE];
__device__ __align__(256) float g_k[(size_t)MROWS * EE];
__device__ __align__(256) float g_v[(size_t)MROWS * EE];
__device__ __align__(256) float g_ctx[(size_t)MROWS * EE];
__device__ __align__(256) __nv_bfloat16 g_ahi[(size_t)MROWS * EE];
__device__ __align__(256) __nv_bfloat16 g_alo[(size_t)MROWS * EE];
__device__ __align__(256) __nv_bfloat16 g_whi[4][(size_t)EE * EE];
__device__ __align__(256) __nv_bfloat16 g_wlo[4][(size_t)EE * EE];

// ---------------------------------------------------------------------------
// Common helpers
// ---------------------------------------------------------------------------
__device__ __forceinline__ void ldsm_x4(unsigned* r, unsigned addr) {
    asm volatile("ldmatrix.sync.aligned.m8n8.x4.shared.b16 {%0,%1,%2,%3}, [%4];\n"
                 : "=r"(r[0]), "=r"(r[1]), "=r"(r[2]), "=r"(r[3]) : "r"(addr));
}
__device__ __forceinline__ void mma16816(float* c, const unsigned* a, const unsigned* b) {
    asm volatile(
        "mma.sync.aligned.m16n8k16.row.col.f32.bf16.bf16.f32 "
        "{%0,%1,%2,%3}, {%4,%5,%6,%7}, {%8,%9}, {%0,%1,%2,%3};\n"
        : "+f"(c[0]), "+f"(c[1]), "+f"(c[2]), "+f"(c[3])
        : "r"(a[0]), "r"(a[1]), "r"(a[2]), "r"(a[3]), "r"(b[0]), "r"(b[1]));
}
// pack two floats into bf16x2 hi and lo (x = hi + lo, ~16-bit mantissa)
__device__ __forceinline__ void split2(float a, float b, unsigned& hi, unsigned& lo) {
    __nv_bfloat16 ha = __float2bfloat16(a), hb = __float2bfloat16(b);
    __nv_bfloat162 H; H.x = ha; H.y = hb;
    __nv_bfloat162 L;
    L.x = __float2bfloat16(a - __bfloat162float(ha));
    L.y = __float2bfloat16(b - __bfloat162float(hb));
    hi = *reinterpret_cast<unsigned*>(&H);
    lo = *reinterpret_cast<unsigned*>(&L);
}
// exp(x) for x <= 0 via exp2 poly — pure FFMA/ALU, no MUFU. ~1e-7 rel err.
__device__ __forceinline__ float fexp_neg(float x) {
    x = fmaxf(x, -80.0f);
    float t  = fmaf(x, 1.4426950408889634f, 12582912.0f);  // round(x*log2e) in mantissa
    float nf = t - 12582912.0f;
    float r  = fmaf(x, 1.4426950408889634f, -nf);          // r in [-0.5, 0.5]
    float p  =             1.5403530393381609e-4f;
    p = fmaf(p, r, 1.3333558146428443e-3f);
    p = fmaf(p, r, 9.6181291076284772e-3f);
    p = fmaf(p, r, 5.5504108664821580e-2f);
    p = fmaf(p, r, 2.4022650695910071e-1f);
    p = fmaf(p, r, 6.9314718055994531e-1f);
    p = fmaf(p, r, 1.0f);
    int ni = __float_as_int(t) - 0x4B400000;               // integer part
    return __int_as_float(__float_as_int(p) + (ni << 23)); // p * 2^ni
}

// ---------------------------------------------------------------------------
// Split fp32 -> (hi, lo) bf16 arrays.
// ---------------------------------------------------------------------------
__global__ __launch_bounds__(256) void split_bf16(
    const float* __restrict__ x,
    __nv_bfloat16* __restrict__ hi, __nv_bfloat16* __restrict__ lo, int n4)
{
    int i = blockIdx.x * 256 + threadIdx.x;
    if (i >= n4) return;
    float4 v = ((const float4*)x)[i];
    unsigned h01, l01, h23, l23;
    split2(v.x, v.y, h01, l01);
    split2(v.z, v.w, h23, l23);
    ((uint2*)hi)[i] = make_uint2(h01, h23);
    ((uint2*)lo)[i] = make_uint2(l01, l23);
}

// ---------------------------------------------------------------------------
// Tensor-core NT GEMM, 3-term bf16 split (unchanged from R3 — verified).
// ---------------------------------------------------------------------------
#define BM 128
#define BN 128
#define BK 32
#define LDT 40
#define TILE_E (BM * LDT)
#define STAGE_E (4 * TILE_E)

__global__ __launch_bounds__(256) void gemm_bf16x3(
    const __nv_bfloat16* __restrict__ Ah, const __nv_bfloat16* __restrict__ Al,
    const __nv_bfloat16* __restrict__ Bh, const __nv_bfloat16* __restrict__ Bl,
    float* __restrict__ C, int M, int N, int K)
{
    extern __shared__ __nv_bfloat16 smem[];
    const int tid  = threadIdx.x;
    const int wid  = tid >> 5;
    const int lane = tid & 31;
    const int warpM = wid & 3;
    const int warpN = wid >> 2;
    const int mBase = blockIdx.y * BM;
    const int nBase = blockIdx.x * BN;

    const unsigned sbase = (unsigned)__cvta_generic_to_shared(smem);
    const int lrow = tid >> 2;
    const int lcol = (tid & 3) * 8;

    float acc[2][8][4];
    #pragma unroll
    for (int t = 0; t < 2; t++)
        #pragma unroll
        for (int j = 0; j < 8; j++)
            #pragma unroll
            for (int e = 0; e < 4; e++) acc[t][j][e] = 0.0f;

    const int nsteps = K / BK;

    {
        #pragma unroll
        for (int c = 0; c < 2; c++) {
            int row = lrow + c * 64;
            uint4 va = *(const uint4*)&Ah[(size_t)(mBase + row) * K + lcol];
            uint4 vb = *(const uint4*)&Al[(size_t)(mBase + row) * K + lcol];
            uint4 vc = *(const uint4*)&Bh[(size_t)(nBase + row) * K + lcol];
            uint4 vd = *(const uint4*)&Bl[(size_t)(nBase + row) * K + lcol];
            int so = row * LDT + lcol;
            *(uint4*)&smem[0 * TILE_E + so] = va;
            *(uint4*)&smem[1 * TILE_E + so] = vb;
            *(uint4*)&smem[2 * TILE_E + so] = vc;
            *(uint4*)&smem[3 * TILE_E + so] = vd;
        }
    }
    __syncthreads();

    uint4 rg[8];
    for (int step = 0; step < nsteps; step++) {
        const int cur = step & 1;

        if (step + 1 < nsteps) {
            const int k0 = (step + 1) * BK;
            #pragma unroll
            for (int c = 0; c < 2; c++) {
                int row = lrow + c * 64;
                rg[c * 4 + 0] = *(const uint4*)&Ah[(size_t)(mBase + row) * K + k0 + lcol];
                rg[c * 4 + 1] = *(const uint4*)&Al[(size_t)(mBase + row) * K + k0 + lcol];
                rg[c * 4 + 2] = *(const uint4*)&Bh[(size_t)(nBase + row) * K + k0 + lcol];
                rg[c * 4 + 3] = *(const uint4*)&Bl[(size_t)(nBase + row) * K + k0 + lcol];
            }
        }

        const unsigned aBaseH = sbase + (cur * STAGE_E + 0 * TILE_E) * 2;
        const unsigned aBaseL = sbase + (cur * STAGE_E + 1 * TILE_E) * 2;
        const unsigned bBaseH = sbase + (cur * STAGE_E + 2 * TILE_E) * 2;
        const unsigned bBaseL = sbase + (cur * STAGE_E + 3 * TILE_E) * 2;

        #pragma unroll
        for (int kk = 0; kk < BK; kk += 16) {
            unsigned fAh[2][4], fAl[2][4];
            const int aCol = kk + ((lane >> 4) << 3);
            #pragma unroll
            for (int t = 0; t < 2; t++) {
                int aRow = warpM * 32 + t * 16 + (lane & 15);
                unsigned off = (unsigned)(aRow * LDT + aCol) * 2;
                ldsm_x4(fAh[t], aBaseH + off);
                ldsm_x4(fAl[t], aBaseL + off);
            }
            #pragma unroll
            for (int np = 0; np < 4; np++) {
                const int n0  = warpN * 64 + np * 16;
                const int grp = lane >> 3, r = lane & 7;
                const int bRow = n0 + ((grp & 2) << 2) + r;
                const int bCol = kk + ((grp & 1) << 3);
                unsigned boff = (unsigned)(bRow * LDT + bCol) * 2;
                unsigned fBh[4], fBl[4];
                ldsm_x4(fBh, bBaseH + boff);
                ldsm_x4(fBl, bBaseL + boff);
                #pragma unroll
                for (int t = 0; t < 2; t++) {
                    mma16816(acc[t][np * 2 + 0], fAh[t], fBh + 0);
                    mma16816(acc[t][np * 2 + 1], fAh[t], fBh + 2);
                    mma16816(acc[t][np * 2 + 0], fAh[t], fBl + 0);
                    mma16816(acc[t][np * 2 + 1], fAh[t], fBl + 2);
                    mma16816(acc[t][np * 2 + 0], fAl[t], fBh + 0);
                    mma16816(acc[t][np * 2 + 1], fAl[t], fBh + 2);
                }
            }
        }

        if (step + 1 < nsteps) {
            const int nxt = 1 - cur;
            __syncthreads();
            #pragma unroll
            for (int c = 0; c < 2; c++) {
                int row = lrow + c * 64;
                int so = nxt * STAGE_E + row * LDT + lcol;
                *(uint4*)&smem[so + 0 * TILE_E] = rg[c * 4 + 0];
                *(uint4*)&smem[so + 1 * TILE_E] = rg[c * 4 + 1];
                *(uint4*)&smem[so + 2 * TILE_E] = rg[c * 4 + 2];
                *(uint4*)&smem[so + 3 * TILE_E] = rg[c * 4 + 3];
            }
            __syncthreads();
        }
    }

    #pragma unroll
    for (int t = 0; t < 2; t++) {
        int row = mBase + warpM * 32 + t * 16 + (lane >> 2);
        #pragma unroll
        for (int j = 0; j < 8; j++) {
            int col = nBase + warpN * 64 + j * 8 + (lane & 3) * 2;
            float2 lo2 = make_float2(acc[t][j][0], acc[t][j][1]);
            float2 hi2 = make_float2(acc[t][j][2], acc[t][j][3]);
            *(float2*)&C[(size_t)row * N + col]       = lo2;
            *(float2*)&C[(size_t)(row + 8) * N + col] = hi2;
        }
    }
}

// ---------------------------------------------------------------------------
// Row LayerNorm in place (unchanged).
// ---------------------------------------------------------------------------
__global__ __launch_bounds__(256) void ln_rows(
    float* __restrict__ X, const float* __restrict__ gamma,
    const float* __restrict__ beta)
{
    float* x = X + (size_t)blockIdx.x * EE;
    const int tid = threadIdx.x;

    float4 v = *(const float4*)&x[tid * 4];
    float s  = v.x + v.y + v.z + v.w;
    float sq = v.x * v.x + v.y * v.y + v.z * v.z + v.w * v.w;

    #pragma unroll
    for (int off = 16; off > 0; off >>= 1) {
        s  += __shfl_xor_sync(0xffffffffu, s,  off);
        sq += __shfl_xor_sync(0xffffffffu, sq, off);
    }
    __shared__ float ss[8], sqs[8];
    const int wid = tid >> 5, lane = tid & 31;
    if (lane == 0) { ss[wid] = s; sqs[wid] = sq; }
    __syncthreads();
    float ts = 0.0f, tsq = 0.0f;
    #pragma unroll
    for (int w = 0; w < 8; w++) { ts += ss[w]; tsq += sqs[w]; }

    const float inv_n = 1.0f / (float)EE;
    float mean = ts * inv_n;
    float var  = tsq * inv_n - mean * mean;
    float rstd = rsqrtf(var + 1e-5f);

    float4 g = *(const float4*)&gamma[tid * 4];
    float4 b = *(const float4*)&beta[tid * 4];
    v.x = (v.x - mean) * rstd * g.x + b.x;
    v.y = (v.y - mean) * rstd * g.y + b.y;
    v.z = (v.z - mean) * rstd * g.z + b.z;
    v.w = (v.w - mean) * rstd * g.w + b.w;
    *(float4*)&x[tid * 4] = v;
}

// ---------------------------------------------------------------------------
// Tensor-core flash attention with 3-term bf16 split and FFMA-poly exp.
// Block = (128 q rows, head h, batch b). 8 warps x 16 q rows. KV tiles of 64.
// Smem (bf16, +8 pad): Qh/Ql [128][72], Kh/Kl [64][72], Vh/Vl (transposed) [64][72].
// ---------------------------------------------------------------------------
#define FLQ 72

__global__ __launch_bounds__(256, 2) void flash_tc(
    const float* __restrict__ Q, const float* __restrict__ K,
    const float* __restrict__ V, float* __restrict__ O)
{
    extern __shared__ __nv_bfloat16 fsm[];
    __nv_bfloat16* Qh = fsm;
    __nv_bfloat16* Ql = Qh + 128 * FLQ;
    __nv_bfloat16* Kh = Ql + 128 * FLQ;
    __nv_bfloat16* Kl = Kh + 64 * FLQ;
    __nv_bfloat16* Vh = Kl + 64 * FLQ;
    __nv_bfloat16* Vl = Vh + 64 * FLQ;

    const int b   = blockIdx.z;
    const int h   = blockIdx.y;
    const int q0  = blockIdx.x * 128;
    const int tid = threadIdx.x;
    const int w   = tid >> 5;
    const int lane = tid & 31;
    const size_t headOff = (size_t)h * DD;

    const unsigned sb = (unsigned)__cvta_generic_to_shared(fsm);
    const unsigned uQh = sb;
    const unsigned uQl = uQh + 128 * FLQ * 2;
    const unsigned uKh = uQl + 128 * FLQ * 2;
    const unsigned uKl = uKh + 64 * FLQ * 2;
    const unsigned uVh = uKl + 64 * FLQ * 2;
    const unsigned uVl = uVh + 64 * FLQ * 2;

    // ---- load Q tile (scaled by 1/sqrt(D)), split to bf16 hi/lo ----
    {
        const int r0 = tid >> 4;
        const int c  = (tid & 15) * 4;
        #pragma unroll
        for (int p = 0; p < 8; p++) {
            int r = r0 + p * 16;
            float4 v = *(const float4*)&Q[((size_t)(b * TT + q0 + r)) * EE + headOff + c];
            v.x *= 0.125f; v.y *= 0.125f; v.z *= 0.125f; v.w *= 0.125f;
            unsigned h01, l01, h23, l23;
            split2(v.x, v.y, h01, l01);
            split2(v.z, v.w, h23, l23);
            *(uint2*)&Qh[r * FLQ + c] = make_uint2(h01, h23);
            *(uint2*)&Ql[r * FLQ + c] = make_uint2(l01, l23);
        }
    }

    // softmax state (rows r and r+8 of this warp's 16)
    float m0 = -1e30f, m1 = -1e30f, l0 = 0.0f, l1 = 0.0f;
    float o[8][4];
    #pragma unroll
    for (int j = 0; j < 8; j++)
        #pragma unroll
        for (int e = 0; e < 4; e++) o[j][e] = 0.0f;

    // fragment geometry (identical formulas to gemm_bf16x3 — verified)
    const int aRow   = w * 16 + (lane & 15);
    const int aColOf = (lane >> 4) << 3;
    const int grp = lane >> 3, rr = lane & 7;
    const int bRowOf = ((grp & 2) << 2) + rr;
    const int bColOf = (grp & 1) << 3;

    for (int kv0 = 0; kv0 < TT; kv0 += 64) {
        __syncthreads();   // previous tile's reads of K/V smem done
        // ---- load K and V tiles (64 rows), split; V transposed ----
        {
            const int r0 = tid >> 4;
            const int c  = (tid & 15) * 4;
            #pragma unroll
            for (int p = 0; p < 4; p++) {
                int r = r0 + p * 16;
                size_t gidx = ((size_t)(b * TT + kv0 + r)) * EE + headOff + c;
                float4 kv = *(const float4*)&K[gidx];
                unsigned h01, l01, h23, l23;
                split2(kv.x, kv.y, h01, l01);
                split2(kv.z, kv.w, h23, l23);
                *(uint2*)&Kh[r * FLQ + c] = make_uint2(h01, h23);
                *(uint2*)&Kl[r * FLQ + c] = make_uint2(l01, l23);

                float4 vv = *(const float4*)&V[gidx];
                float ve[4] = {vv.x, vv.y, vv.z, vv.w};
                #pragma unroll
                for (int i = 0; i < 4; i++) {
                    __nv_bfloat16 hh = __float2bfloat16(ve[i]);
                    Vh[(c + i) * FLQ + r] = hh;
                    Vl[(c + i) * FLQ + r] = __float2bfloat16(ve[i] - __bfloat162float(hh));
                }
            }
        }
        __syncthreads();

        // ---- S = Q K^T (3-term split), 16x64 per warp ----
        float s[8][4];
        #pragma unroll
        for (int j = 0; j < 8; j++)
            #pragma unroll
            for (int e = 0; e < 4; e++) s[j][e] = 0.0f;

        #pragma unroll
        for (int t = 0; t < 4; t++) {
            unsigned aQh[4], aQl[4];
            unsigned aoff = (unsigned)(aRow * FLQ + t * 16 + aColOf) * 2;
            ldsm_x4(aQh, uQh + aoff);
            ldsm_x4(aQl, uQl + aoff);
            #pragma unroll
            for (int j = 0; j < 4; j++) {
                unsigned boff = (unsigned)((j * 16 + bRowOf) * FLQ + t * 16 + bColOf) * 2;
                unsigned fKh[4], fKl[4];
                ldsm_x4(fKh, uKh + boff);
                ldsm_x4(fKl, uKl + boff);
                mma16816(s[2 * j + 0], aQh, fKh + 0);
                mma16816(s[2 * j + 1], aQh, fKh + 2);
                mma16816(s[2 * j + 0], aQh, fKl + 0);
                mma16816(s[2 * j + 1], aQh, fKl + 2);
                mma16816(s[2 * j + 0], aQl, fKh + 0);
                mma16816(s[2 * j + 1], aQl, fKh + 2);
            }
        }

        // ---- online softmax (rows lane>>2 and +8) ----
        float mx0 = -1e30f, mx1 = -1e30f;
        #pragma unroll
        for (int j = 0; j < 8; j++) {
            mx0 = fmaxf(mx0, fmaxf(s[j][0], s[j][1]));
            mx1 = fmaxf(mx1, fmaxf(s[j][2], s[j][3]));
        }
        mx0 = fmaxf(mx0, __shfl_xor_sync(0xffffffffu, mx0, 1));
        mx0 = fmaxf(mx0, __shfl_xor_sync(0xffffffffu, mx0, 2));
        mx1 = fmaxf(mx1, __shfl_xor_sync(0xffffffffu, mx1, 1));
        mx1 = fmaxf(mx1, __shfl_xor_sync(0xffffffffu, mx1, 2));

        float mn0 = fmaxf(m0, mx0), mn1 = fmaxf(m1, mx1);
        float c0 = fexp_neg(m0 - mn0), c1 = fexp_neg(m1 - mn1);
        m0 = mn0; m1 = mn1;

        float rs0 = 0.0f, rs1 = 0.0f;
        #pragma unroll
        for (int j = 0; j < 8; j++) {
            s[j][0] = fexp_neg(s[j][0] - mn0); rs0 += s[j][0];
            s[j][1] = fexp_neg(s[j][1] - mn0); rs0 += s[j][1];
            s[j][2] = fexp_neg(s[j][2] - mn1); rs1 += s[j][2];
            s[j][3] = fexp_neg(s[j][3] - mn1); rs1 += s[j][3];
        }
        rs0 += __shfl_xor_sync(0xffffffffu, rs0, 1);
        rs0 += __shfl_xor_sync(0xffffffffu, rs0, 2);
        rs1 += __shfl_xor_sync(0xffffffffu, rs1, 1);
        rs1 += __shfl_xor_sync(0xffffffffu, rs1, 2);
        l0 = fmaf(l0, c0, rs0);
        l1 = fmaf(l1, c1, rs1);

        #pragma unroll
        for (int j = 0; j < 8; j++) {
            o[j][0] *= c0; o[j][1] *= c0;
            o[j][2] *= c1; o[j][3] *= c1;
        }

        // ---- O += P V (3-term split; P from S fragments, V transposed) ----
        #pragma unroll
        for (int t = 0; t < 4; t++) {
            unsigned aPh[4], aPl[4];
            split2(s[2 * t][0],     s[2 * t][1],     aPh[0], aPl[0]);
            split2(s[2 * t][2],     s[2 * t][3],     aPh[1], aPl[1]);
            split2(s[2 * t + 1][0], s[2 * t + 1][1], aPh[2], aPl[2]);
            split2(s[2 * t + 1][2], s[2 * t + 1][3], aPh[3], aPl[3]);
            #pragma unroll
            for (int n = 0; n < 4; n++) {
                unsigned boff = (unsigned)((n * 16 + bRowOf) * FLQ + t * 16 + bColOf) * 2;
                unsigned fVh[4], fVl[4];
                ldsm_x4(fVh, uVh + boff);
                ldsm_x4(fVl, uVl + boff);
                mma16816(o[2 * n + 0], aPh, fVh + 0);
                mma16816(o[2 * n + 1], aPh, fVh + 2);
                mma16816(o[2 * n + 0], aPh, fVl + 0);
                mma16816(o[2 * n + 1], aPh, fVl + 2);
                mma16816(o[2 * n + 0], aPl, fVh + 0);
                mma16816(o[2 * n + 1], aPl, fVh + 2);
            }
        }
    }

    // ---- epilogue: normalize and store ----
    float inv0 = 1.0f / l0, inv1 = 1.0f / l1;
    int row0 = b * TT + q0 + w * 16 + (lane >> 2);
    #pragma unroll
    for (int j = 0; j < 8; j++) {
        size_t col = headOff + j * 8 + (lane & 3) * 2;
        *(float2*)&O[(size_t)row0 * EE + col] =
            make_float2(o[j][0] * inv0, o[j][1] * inv0);
        *(float2*)&O[(size_t)(row0 + 8) * EE + col] =
            make_float2(o[j][2] * inv1, o[j][3] * inv1);
    }
}

// ---------------------------------------------------------------------------
// Launch
// ---------------------------------------------------------------------------
extern "C" void kernel_launch(void* const* d_in, const int* in_sizes, int n_in,
                              void* d_out, int out_size)
{
    const float* xq  = (const float*)d_in[0];
    const float* xkv = (const float*)d_in[1];
    const float* W[4] = { (const float*)d_in[2], (const float*)d_in[3],
                          (const float*)d_in[4], (const float*)d_in[5] };
    const float* qg  = (const float*)d_in[6];
    const float* qb  = (const float*)d_in[7];
    const float* kg  = (const float*)d_in[8];
    const float* kb  = (const float*)d_in[9];

    float *q, *k, *v, *ctx;
    __nv_bfloat16 *ahi, *alo, *whi, *wlo;
    cudaGetSymbolAddress((void**)&q,   g_q);
    cudaGetSymbolAddress((void**)&k,   g_k);
    cudaGetSymbolAddress((void**)&v,   g_v);
    cudaGetSymbolAddress((void**)&ctx, g_ctx);
    cudaGetSymbolAddress((void**)&ahi, g_ahi);
    cudaGetSymbolAddress((void**)&alo, g_alo);
    cudaGetSymbolAddress((void**)&whi, g_whi);
    cudaGetSymbolAddress((void**)&wlo, g_wlo);

    const size_t wsz = (size_t)EE * EE;
    const int nW4 = (int)(wsz / 4);
    const int nA4 = (int)((size_t)MROWS * EE / 4);

    int smemGemm  = 2 * STAGE_E * 2;                 // 81920 B
    int smemFlash = (2 * 128 + 4 * 64) * FLQ * 2;    // 73728 B
    cudaFuncSetAttribute((const void*)gemm_bf16x3,
                         cudaFuncAttributeMaxDynamicSharedMemorySize, smemGemm);
    cudaFuncSetAttribute((const void*)flash_tc,
                         cudaFuncAttributeMaxDynamicSharedMemorySize, smemFlash);

    for (int i = 0; i < 4; i++)
        split_bf16<<<(nW4 + 255) / 256, 256>>>(W[i], whi + i * wsz, wlo + i * wsz, nW4);

    dim3 gGrid(EE / BN, MROWS / BM);   // (8, 64)

    split_bf16<<<(nA4 + 255) / 256, 256>>>(xq, ahi, alo, nA4);
    gemm_bf16x3<<<gGrid, 256, smemGemm>>>(ahi, alo, whi + 0 * wsz, wlo + 0 * wsz,
                                          q, MROWS, EE, EE);
    split_bf16<<<(nA4 + 255) / 256, 256>>>(xkv, ahi, alo, nA4);
    gemm_bf16x3<<<gGrid, 256, smemGemm>>>(ahi, alo, whi + 1 * wsz, wlo + 1 * wsz,
                                          k, MROWS, EE, EE);
    gemm_bf16x3<<<gGrid, 256, smemGemm>>>(ahi, alo, whi + 2 * wsz, wlo + 2 * wsz,
                                          v, MROWS, EE, EE);

    ln_rows<<<MROWS, 256>>>(q, qg, qb);
    ln_rows<<<MROWS, 256>>>(k, kg, kb);

    flash_tc<<<dim3(TT / 128, HH, BBATCH), 256, smemFlash>>>(q, k, v, ctx);

    split_bf16<<<(nA4 + 255) / 256, 256>>>(ctx, ahi, alo, nA4);
    gemm_bf16x3<<<gGrid, 256, smemGemm>>>(ahi, alo, whi + 3 * wsz, wlo + 3 * wsz,
                                          (float*)d_out, MROWS, EE, EE);
}

// round 6
// speedup vs baseline: 2.4675x; 1.1083x over previous
#include <cuda_runtime.h>
#include <cuda_bf16.h>
#include <math.h>

// Problem constants
#define EE   1024
#define TT   2048
#define BBATCH 4
#define HH   16
#define DD   64
#define MROWS (BBATCH * TT)   // 8192

// ---------------------------------------------------------------------------
// Scratch: __device__ globals (allocation-free per harness rules)
// ---------------------------------------------------------------------------
__device__ __align__(256) float g_q[(size_t)MROWS * EE];
__device__ __align__(256) float g_k[(size_t)MROWS * EE];
__device__ __align__(256) float g_v[(size_t)MROWS * EE];
__device__ __align__(256) float g_ctx[(size_t)MROWS * EE];
__device__ __align__(256) __nv_bfloat16 g_ahi[(size_t)MROWS * EE];
__device__ __align__(256) __nv_bfloat16 g_alo[(size_t)MROWS * EE];
__device__ __align__(256) __nv_bfloat16 g_whi[4][(size_t)EE * EE];
__device__ __align__(256) __nv_bfloat16 g_wlo[4][(size_t)EE * EE];

// ---------------------------------------------------------------------------
// Common helpers
// ---------------------------------------------------------------------------
__device__ __forceinline__ void ldsm_x4(unsigned* r, unsigned addr) {
    asm volatile("ldmatrix.sync.aligned.m8n8.x4.shared.b16 {%0,%1,%2,%3}, [%4];\n"
                 : "=r"(r[0]), "=r"(r[1]), "=r"(r[2]), "=r"(r[3]) : "r"(addr));
}
__device__ __forceinline__ void mma16816(float* c, const unsigned* a, const unsigned* b) {
    asm volatile(
        "mma.sync.aligned.m16n8k16.row.col.f32.bf16.bf16.f32 "
        "{%0,%1,%2,%3}, {%4,%5,%6,%7}, {%8,%9}, {%0,%1,%2,%3};\n"
        : "+f"(c[0]), "+f"(c[1]), "+f"(c[2]), "+f"(c[3])
        : "r"(a[0]), "r"(a[1]), "r"(a[2]), "r"(a[3]), "r"(b[0]), "r"(b[1]));
}
__device__ __forceinline__ void cpa16(unsigned dst, const void* src) {
    asm volatile("cp.async.cg.shared.global [%0], [%1], 16;"
                 :: "r"(dst), "l"(src) : "memory");
}
__device__ __forceinline__ void split2(float a, float b, unsigned& hi, unsigned& lo) {
    __nv_bfloat16 ha = __float2bfloat16(a), hb = __float2bfloat16(b);
    __nv_bfloat162 H; H.x = ha; H.y = hb;
    __nv_bfloat162 L;
    L.x = __float2bfloat16(a - __bfloat162float(ha));
    L.y = __float2bfloat16(b - __bfloat162float(hb));
    hi = *reinterpret_cast<unsigned*>(&H);
    lo = *reinterpret_cast<unsigned*>(&L);
}
__device__ __forceinline__ float fexp_neg(float x) {
    x = fmaxf(x, -80.0f);
    float t  = fmaf(x, 1.4426950408889634f, 12582912.0f);
    float nf = t - 12582912.0f;
    float r  = fmaf(x, 1.4426950408889634f, -nf);
    float p  =             1.5403530393381609e-4f;
    p = fmaf(p, r, 1.3333558146428443e-3f);
    p = fmaf(p, r, 9.6181291076284772e-3f);
    p = fmaf(p, r, 5.5504108664821580e-2f);
    p = fmaf(p, r, 2.4022650695910071e-1f);
    p = fmaf(p, r, 6.9314718055994531e-1f);
    p = fmaf(p, r, 1.0f);
    int ni = __float_as_int(t) - 0x4B400000;
    return __int_as_float(__float_as_int(p) + (ni << 23));
}

// ---------------------------------------------------------------------------
// Split fp32 -> (hi, lo) bf16 arrays.
// ---------------------------------------------------------------------------
__global__ __launch_bounds__(256) void split_bf16(
    const float* __restrict__ x,
    __nv_bfloat16* __restrict__ hi, __nv_bfloat16* __restrict__ lo, int n4)
{
    int i = blockIdx.x * 256 + threadIdx.x;
    if (i >= n4) return;
    float4 v = ((const float4*)x)[i];
    unsigned h01, l01, h23, l23;
    split2(v.x, v.y, h01, l01);
    split2(v.z, v.w, h23, l23);
    ((uint2*)hi)[i] = make_uint2(h01, h23);
    ((uint2*)lo)[i] = make_uint2(l01, l23);
}

// ---------------------------------------------------------------------------
// Tensor-core NT GEMM, 3-term bf16 split, cp.async 2-stage pipeline.
// Block tile 128x128x32, 8 warps (warp tile 32x64). 2 CTAs/SM.
// ---------------------------------------------------------------------------
#define BM 128
#define BN 128
#define BK 32
#define LDT 40
#define TILE_E (BM * LDT)
#define STAGE_E (4 * TILE_E)

__global__ __launch_bounds__(256, 2) void gemm_bf16x3(
    const __nv_bfloat16* __restrict__ Ah, const __nv_bfloat16* __restrict__ Al,
    const __nv_bfloat16* __restrict__ Bh, const __nv_bfloat16* __restrict__ Bl,
    float* __restrict__ C, int M, int N, int K)
{
    extern __shared__ __nv_bfloat16 smem[];
    const int tid  = threadIdx.x;
    const int wid  = tid >> 5;
    const int lane = tid & 31;
    const int warpM = wid & 3;
    const int warpN = wid >> 2;
    const int mBase = blockIdx.y * BM;
    const int nBase = blockIdx.x * BN;

    const unsigned sbase = (unsigned)__cvta_generic_to_shared(smem);
    const int lrow = tid >> 2;
    const int lcol = (tid & 3) * 8;

    const int nsteps = K / BK;   // 32

    // async-copy one stage (4 tiles x 2 rows/thread x 16B)
    auto issue_stage = [&](int stage) {
        const int buf = stage & 1;
        const int k0  = stage * BK;
        const unsigned base = sbase + (unsigned)(buf * STAGE_E) * 2;
        #pragma unroll
        for (int c = 0; c < 2; c++) {
            int row = lrow + c * 64;
            unsigned so = base + (unsigned)(row * LDT + lcol) * 2;
            cpa16(so + 0u * TILE_E * 2, &Ah[(size_t)(mBase + row) * K + k0 + lcol]);
            cpa16(so + 1u * TILE_E * 2, &Al[(size_t)(mBase + row) * K + k0 + lcol]);
            cpa16(so + 2u * TILE_E * 2, &Bh[(size_t)(nBase + row) * K + k0 + lcol]);
            cpa16(so + 3u * TILE_E * 2, &Bl[(size_t)(nBase + row) * K + k0 + lcol]);
        }
        asm volatile("cp.async.commit_group;" ::: "memory");
    };

    float acc[2][8][4];
    #pragma unroll
    for (int t = 0; t < 2; t++)
        #pragma unroll
        for (int j = 0; j < 8; j++)
            #pragma unroll
            for (int e = 0; e < 4; e++) acc[t][j][e] = 0.0f;

    issue_stage(0);
    issue_stage(1);

    for (int step = 0; step < nsteps; step++) {
        const int cur = step & 1;
        if (step + 1 < nsteps)
            asm volatile("cp.async.wait_group 1;" ::: "memory");
        else
            asm volatile("cp.async.wait_group 0;" ::: "memory");
        __syncthreads();

        const unsigned aBaseH = sbase + (cur * STAGE_E + 0 * TILE_E) * 2;
        const unsigned aBaseL = sbase + (cur * STAGE_E + 1 * TILE_E) * 2;
        const unsigned bBaseH = sbase + (cur * STAGE_E + 2 * TILE_E) * 2;
        const unsigned bBaseL = sbase + (cur * STAGE_E + 3 * TILE_E) * 2;

        #pragma unroll
        for (int kk = 0; kk < BK; kk += 16) {
            unsigned fAh[2][4], fAl[2][4];
            const int aCol = kk + ((lane >> 4) << 3);
            #pragma unroll
            for (int t = 0; t < 2; t++) {
                int aRow = warpM * 32 + t * 16 + (lane & 15);
                unsigned off = (unsigned)(aRow * LDT + aCol) * 2;
                ldsm_x4(fAh[t], aBaseH + off);
                ldsm_x4(fAl[t], aBaseL + off);
            }
            #pragma unroll
            for (int np = 0; np < 4; np++) {
                const int n0  = warpN * 64 + np * 16;
                const int grp = lane >> 3, r = lane & 7;
                const int bRow = n0 + ((grp & 2) << 2) + r;
                const int bCol = kk + ((grp & 1) << 3);
                unsigned boff = (unsigned)(bRow * LDT + bCol) * 2;
                unsigned fBh[4], fBl[4];
                ldsm_x4(fBh, bBaseH + boff);
                ldsm_x4(fBl, bBaseL + boff);
                #pragma unroll
                for (int t = 0; t < 2; t++) {
                    mma16816(acc[t][np * 2 + 0], fAh[t], fBh + 0);
                    mma16816(acc[t][np * 2 + 1], fAh[t], fBh + 2);
                    mma16816(acc[t][np * 2 + 0], fAh[t], fBl + 0);
                    mma16816(acc[t][np * 2 + 1], fAh[t], fBl + 2);
                    mma16816(acc[t][np * 2 + 0], fAl[t], fBh + 0);
                    mma16816(acc[t][np * 2 + 1], fAl[t], fBh + 2);
                }
            }
        }

        __syncthreads();                     // all warps done reading buf `cur`
        if (step + 2 < nsteps) issue_stage(step + 2);
    }

    #pragma unroll
    for (int t = 0; t < 2; t++) {
        int row = mBase + warpM * 32 + t * 16 + (lane >> 2);
        #pragma unroll
        for (int j = 0; j < 8; j++) {
            int col = nBase + warpN * 64 + j * 8 + (lane & 3) * 2;
            float2 lo2 = make_float2(acc[t][j][0], acc[t][j][1]);
            float2 hi2 = make_float2(acc[t][j][2], acc[t][j][3]);
            *(float2*)&C[(size_t)row * N + col]       = lo2;
            *(float2*)&C[(size_t)(row + 8) * N + col] = hi2;
        }
    }
}

// ---------------------------------------------------------------------------
// Row LayerNorm in place (unchanged).
// ---------------------------------------------------------------------------
__global__ __launch_bounds__(256) void ln_rows(
    float* __restrict__ X, const float* __restrict__ gamma,
    const float* __restrict__ beta)
{
    float* x = X + (size_t)blockIdx.x * EE;
    const int tid = threadIdx.x;

    float4 v = *(const float4*)&x[tid * 4];
    float s  = v.x + v.y + v.z + v.w;
    float sq = v.x * v.x + v.y * v.y + v.z * v.z + v.w * v.w;

    #pragma unroll
    for (int off = 16; off > 0; off >>= 1) {
        s  += __shfl_xor_sync(0xffffffffu, s,  off);
        sq += __shfl_xor_sync(0xffffffffu, sq, off);
    }
    __shared__ float ss[8], sqs[8];
    const int wid = tid >> 5, lane = tid & 31;
    if (lane == 0) { ss[wid] = s; sqs[wid] = sq; }
    __syncthreads();
    float ts = 0.0f, tsq = 0.0f;
    #pragma unroll
    for (int w = 0; w < 8; w++) { ts += ss[w]; tsq += sqs[w]; }

    const float inv_n = 1.0f / (float)EE;
    float mean = ts * inv_n;
    float var  = tsq * inv_n - mean * mean;
    float rstd = rsqrtf(var + 1e-5f);

    float4 g = *(const float4*)&gamma[tid * 4];
    float4 b = *(const float4*)&beta[tid * 4];
    v.x = (v.x - mean) * rstd * g.x + b.x;
    v.y = (v.y - mean) * rstd * g.y + b.y;
    v.z = (v.z - mean) * rstd * g.z + b.z;
    v.w = (v.w - mean) * rstd * g.w + b.w;
    *(float4*)&x[tid * 4] = v;
}

// ---------------------------------------------------------------------------
// Tensor-core flash attention (unchanged from R4 — verified).
// ---------------------------------------------------------------------------
#define FLQ 72

__global__ __launch_bounds__(256, 2) void flash_tc(
    const float* __restrict__ Q, const float* __restrict__ K,
    const float* __restrict__ V, float* __restrict__ O)
{
    extern __shared__ __nv_bfloat16 fsm[];
    __nv_bfloat16* Qh = fsm;
    __nv_bfloat16* Ql = Qh + 128 * FLQ;
    __nv_bfloat16* Kh = Ql + 128 * FLQ;
    __nv_bfloat16* Kl = Kh + 64 * FLQ;
    __nv_bfloat16* Vh = Kl + 64 * FLQ;
    __nv_bfloat16* Vl = Vh + 64 * FLQ;

    const int b   = blockIdx.z;
    const int h   = blockIdx.y;
    const int q0  = blockIdx.x * 128;
    const int tid = threadIdx.x;
    const int w   = tid >> 5;
    const int lane = tid & 31;
    const size_t headOff = (size_t)h * DD;

    const unsigned sb = (unsigned)__cvta_generic_to_shared(fsm);
    const unsigned uQh = sb;
    const unsigned uQl = uQh + 128 * FLQ * 2;
    const unsigned uKh = uQl + 128 * FLQ * 2;
    const unsigned uKl = uKh + 64 * FLQ * 2;
    const unsigned uVh = uKl + 64 * FLQ * 2;
    const unsigned uVl = uVh + 64 * FLQ * 2;

    {
        const int r0 = tid >> 4;
        const int c  = (tid & 15) * 4;
        #pragma unroll
        for (int p = 0; p < 8; p++) {
            int r = r0 + p * 16;
            float4 v = *(const float4*)&Q[((size_t)(b * TT + q0 + r)) * EE + headOff + c];
            v.x *= 0.125f; v.y *= 0.125f; v.z *= 0.125f; v.w *= 0.125f;
            unsigned h01, l01, h23, l23;
            split2(v.x, v.y, h01, l01);
            split2(v.z, v.w, h23, l23);
            *(uint2*)&Qh[r * FLQ + c] = make_uint2(h01, h23);
            *(uint2*)&Ql[r * FLQ + c] = make_uint2(l01, l23);
        }
    }

    float m0 = -1e30f, m1 = -1e30f, l0 = 0.0f, l1 = 0.0f;
    float o[8][4];
    #pragma unroll
    for (int j = 0; j < 8; j++)
        #pragma unroll
        for (int e = 0; e < 4; e++) o[j][e] = 0.0f;

    const int aRow   = w * 16 + (lane & 15);
    const int aColOf = (lane >> 4) << 3;
    const int grp = lane >> 3, rr = lane & 7;
    const int bRowOf = ((grp & 2) << 2) + rr;
    const int bColOf = (grp & 1) << 3;

    for (int kv0 = 0; kv0 < TT; kv0 += 64) {
        __syncthreads();
        {
            const int r0 = tid >> 4;
            const int c  = (tid & 15) * 4;
            #pragma unroll
            for (int p = 0; p < 4; p++) {
                int r = r0 + p * 16;
                size_t gidx = ((size_t)(b * TT + kv0 + r)) * EE + headOff + c;
                float4 kv = *(const float4*)&K[gidx];
                unsigned h01, l01, h23, l23;
                split2(kv.x, kv.y, h01, l01);
                split2(kv.z, kv.w, h23, l23);
                *(uint2*)&Kh[r * FLQ + c] = make_uint2(h01, h23);
                *(uint2*)&Kl[r * FLQ + c] = make_uint2(l01, l23);

                float4 vv = *(const float4*)&V[gidx];
                float ve[4] = {vv.x, vv.y, vv.z, vv.w};
                #pragma unroll
                for (int i = 0; i < 4; i++) {
                    __nv_bfloat16 hh = __float2bfloat16(ve[i]);
                    Vh[(c + i) * FLQ + r] = hh;
                    Vl[(c + i) * FLQ + r] = __float2bfloat16(ve[i] - __bfloat162float(hh));
                }
            }
        }
        __syncthreads();

        float s[8][4];
        #pragma unroll
        for (int j = 0; j < 8; j++)
            #pragma unroll
            for (int e = 0; e < 4; e++) s[j][e] = 0.0f;

        #pragma unroll
        for (int t = 0; t < 4; t++) {
            unsigned aQh[4], aQl[4];
            unsigned aoff = (unsigned)(aRow * FLQ + t * 16 + aColOf) * 2;
            ldsm_x4(aQh, uQh + aoff);
            ldsm_x4(aQl, uQl + aoff);
            #pragma unroll
            for (int j = 0; j < 4; j++) {
                unsigned boff = (unsigned)((j * 16 + bRowOf) * FLQ + t * 16 + bColOf) * 2;
                unsigned fKh[4], fKl[4];
                ldsm_x4(fKh, uKh + boff);
                ldsm_x4(fKl, uKl + boff);
                mma16816(s[2 * j + 0], aQh, fKh + 0);
                mma16816(s[2 * j + 1], aQh, fKh + 2);
                mma16816(s[2 * j + 0], aQh, fKl + 0);
                mma16816(s[2 * j + 1], aQh, fKl + 2);
                mma16816(s[2 * j + 0], aQl, fKh + 0);
                mma16816(s[2 * j + 1], aQl, fKh + 2);
            }
        }

        float mx0 = -1e30f, mx1 = -1e30f;
        #pragma unroll
        for (int j = 0; j < 8; j++) {
            mx0 = fmaxf(mx0, fmaxf(s[j][0], s[j][1]));
            mx1 = fmaxf(mx1, fmaxf(s[j][2], s[j][3]));
        }
        mx0 = fmaxf(mx0, __shfl_xor_sync(0xffffffffu, mx0, 1));
        mx0 = fmaxf(mx0, __shfl_xor_sync(0xffffffffu, mx0, 2));
        mx1 = fmaxf(mx1, __shfl_xor_sync(0xffffffffu, mx1, 1));
        mx1 = fmaxf(mx1, __shfl_xor_sync(0xffffffffu, mx1, 2));

        float mn0 = fmaxf(m0, mx0), mn1 = fmaxf(m1, mx1);
        float c0 = fexp_neg(m0 - mn0), c1 = fexp_neg(m1 - mn1);
        m0 = mn0; m1 = mn1;

        float rs0 = 0.0f, rs1 = 0.0f;
        #pragma unroll
        for (int j = 0; j < 8; j++) {
            s[j][0] = fexp_neg(s[j][0] - mn0); rs0 += s[j][0];
            s[j][1] = fexp_neg(s[j][1] - mn0); rs0 += s[j][1];
            s[j][2] = fexp_neg(s[j][2] - mn1); rs1 += s[j][2];
            s[j][3] = fexp_neg(s[j][3] - mn1); rs1 += s[j][3];
        }
        rs0 += __shfl_xor_sync(0xffffffffu, rs0, 1);
        rs0 += __shfl_xor_sync(0xffffffffu, rs0, 2);
        rs1 += __shfl_xor_sync(0xffffffffu, rs1, 1);
        rs1 += __shfl_xor_sync(0xffffffffu, rs1, 2);
        l0 = fmaf(l0, c0, rs0);
        l1 = fmaf(l1, c1, rs1);

        #pragma unroll
        for (int j = 0; j < 8; j++) {
            o[j][0] *= c0; o[j][1] *= c0;
            o[j][2] *= c1; o[j][3] *= c1;
        }

        #pragma unroll
        for (int t = 0; t < 4; t++) {
            unsigned aPh[4], aPl[4];
            split2(s[2 * t][0],     s[2 * t][1],     aPh[0], aPl[0]);
            split2(s[2 * t][2],     s[2 * t][3],     aPh[1], aPl[1]);
            split2(s[2 * t + 1][0], s[2 * t + 1][1], aPh[2], aPl[2]);
            split2(s[2 * t + 1][2], s[2 * t + 1][3], aPh[3], aPl[3]);
            #pragma unroll
            for (int n = 0; n < 4; n++) {
                unsigned boff = (unsigned)((n * 16 + bRowOf) * FLQ + t * 16 + bColOf) * 2;
                unsigned fVh[4], fVl[4];
                ldsm_x4(fVh, uVh + boff);
                ldsm_x4(fVl, uVl + boff);
                mma16816(o[2 * n + 0], aPh, fVh + 0);
                mma16816(o[2 * n + 1], aPh, fVh + 2);
                mma16816(o[2 * n + 0], aPh, fVl + 0);
                mma16816(o[2 * n + 1], aPh, fVl + 2);
                mma16816(o[2 * n + 0], aPl, fVh + 0);
                mma16816(o[2 * n + 1], aPl, fVh + 2);
            }
        }
    }

    float inv0 = 1.0f / l0, inv1 = 1.0f / l1;
    int row0 = b * TT + q0 + w * 16 + (lane >> 2);
    #pragma unroll
    for (int j = 0; j < 8; j++) {
        size_t col = headOff + j * 8 + (lane & 3) * 2;
        *(float2*)&O[(size_t)row0 * EE + col] =
            make_float2(o[j][0] * inv0, o[j][1] * inv0);
        *(float2*)&O[(size_t)(row0 + 8) * EE + col] =
            make_float2(o[j][2] * inv1, o[j][3] * inv1);
    }
}

// ---------------------------------------------------------------------------
// Launch
// ---------------------------------------------------------------------------
extern "C" void kernel_launch(void* const* d_in, const int* in_sizes, int n_in,
                              void* d_out, int out_size)
{
    const float* xq  = (const float*)d_in[0];
    const float* xkv = (const float*)d_in[1];
    const float* W[4] = { (const float*)d_in[2], (const float*)d_in[3],
                          (const float*)d_in[4], (const float*)d_in[5] };
    const float* qg  = (const float*)d_in[6];
    const float* qb  = (const float*)d_in[7];
    const float* kg  = (const float*)d_in[8];
    const float* kb  = (const float*)d_in[9];

    float *q, *k, *v, *ctx;
    __nv_bfloat16 *ahi, *alo, *whi, *wlo;
    cudaGetSymbolAddress((void**)&q,   g_q);
    cudaGetSymbolAddress((void**)&k,   g_k);
    cudaGetSymbolAddress((void**)&v,   g_v);
    cudaGetSymbolAddress((void**)&ctx, g_ctx);
    cudaGetSymbolAddress((void**)&ahi, g_ahi);
    cudaGetSymbolAddress((void**)&alo, g_alo);
    cudaGetSymbolAddress((void**)&whi, g_whi);
    cudaGetSymbolAddress((void**)&wlo, g_wlo);

    const size_t wsz = (size_t)EE * EE;
    const int nW4 = (int)(wsz / 4);
    const int nA4 = (int)((size_t)MROWS * EE / 4);

    int smemGemm  = 2 * STAGE_E * 2;                 // 81920 B
    int smemFlash = (2 * 128 + 4 * 64) * FLQ * 2;    // 73728 B
    cudaFuncSetAttribute((const void*)gemm_bf16x3,
                         cudaFuncAttributeMaxDynamicSharedMemorySize, smemGemm);
    cudaFuncSetAttribute((const void*)flash_tc,
                         cudaFuncAttributeMaxDynamicSharedMemorySize, smemFlash);

    for (int i = 0; i < 4; i++)
        split_bf16<<<(nW4 + 255) / 256, 256>>>(W[i], whi + i * wsz, wlo + i * wsz, nW4);

    dim3 gGrid(EE / BN, MROWS / BM);   // (8, 64)

    split_bf16<<<(nA4 + 255) / 256, 256>>>(xq, ahi, alo, nA4);
    gemm_bf16x3<<<gGrid, 256, smemGemm>>>(ahi, alo, whi + 0 * wsz, wlo + 0 * wsz,
                                          q, MROWS, EE, EE);
    split_bf16<<<(nA4 + 255) / 256, 256>>>(xkv, ahi, alo, nA4);
    gemm_bf16x3<<<gGrid, 256, smemGemm>>>(ahi, alo, whi + 1 * wsz, wlo + 1 * wsz,
                                          k, MROWS, EE, EE);
    gemm_bf16x3<<<gGrid, 256, smemGemm>>>(ahi, alo, whi + 2 * wsz, wlo + 2 * wsz,
                                          v, MROWS, EE, EE);

    ln_rows<<<MROWS, 256>>>(q, qg, qb);
    ln_rows<<<MROWS, 256>>>(k, kg, kb);

    flash_tc<<<dim3(TT / 128, HH, BBATCH), 256, smemFlash>>>(q, k, v, ctx);

    split_bf16<<<(nA4 + 255) / 256, 256>>>(ctx, ahi, alo, nA4);
    gemm_bf16x3<<<gGrid, 256, smemGemm>>>(ahi, alo, whi + 3 * wsz, wlo + 3 * wsz,
                                          (float*)d_out, MROWS, EE, EE);
}

// round 9
// speedup vs baseline: 2.5622x; 1.0384x over previous
#include <cuda_runtime.h>
#include <cuda_bf16.h>
#include <math.h>

// Problem constants
#define EE   1024
#define TT   2048
#define BBATCH 4
#define HH   16
#define DD   64
#define MROWS (BBATCH * TT)   // 8192

// ---------------------------------------------------------------------------
// Scratch: __device__ globals (allocation-free per harness rules)
// ---------------------------------------------------------------------------
__device__ __align__(256) float g_q[(size_t)MROWS * EE];
__device__ __align__(256) float g_k[(size_t)MROWS * EE];
__device__ __align__(256) float g_v[(size_t)MROWS * EE];
__device__ __align__(256) float g_ctx[(size_t)MROWS * EE];
__device__ __align__(256) __nv_bfloat16 g_ahi[(size_t)MROWS * EE];
__device__ __align__(256) __nv_bfloat16 g_alo[(size_t)MROWS * EE];
__device__ __align__(256) __nv_bfloat16 g_whi[4][(size_t)EE * EE];
__device__ __align__(256) __nv_bfloat16 g_wlo[4][(size_t)EE * EE];

// ---------------------------------------------------------------------------
// Common helpers
// ---------------------------------------------------------------------------
__device__ __forceinline__ void ldsm_x4(unsigned* r, unsigned addr) {
    asm volatile("ldmatrix.sync.aligned.m8n8.x4.shared.b16 {%0,%1,%2,%3}, [%4];\n"
                 : "=r"(r[0]), "=r"(r[1]), "=r"(r[2]), "=r"(r[3]) : "r"(addr));
}
__device__ __forceinline__ void mma16816(float* c, const unsigned* a, const unsigned* b) {
    asm volatile(
        "mma.sync.aligned.m16n8k16.row.col.f32.bf16.bf16.f32 "
        "{%0,%1,%2,%3}, {%4,%5,%6,%7}, {%8,%9}, {%0,%1,%2,%3};\n"
        : "+f"(c[0]), "+f"(c[1]), "+f"(c[2]), "+f"(c[3])
        : "r"(a[0]), "r"(a[1]), "r"(a[2]), "r"(a[3]), "r"(b[0]), "r"(b[1]));
}
__device__ __forceinline__ void cpa16(unsigned dst, const void* src) {
    asm volatile("cp.async.cg.shared.global [%0], [%1], 16;"
                 :: "r"(dst), "l"(src) : "memory");
}
__device__ __forceinline__ void split2(float a, float b, unsigned& hi, unsigned& lo) {
    __nv_bfloat16 ha = __float2bfloat16(a), hb = __float2bfloat16(b);
    __nv_bfloat162 H; H.x = ha; H.y = hb;
    __nv_bfloat162 L;
    L.x = __float2bfloat16(a - __bfloat162float(ha));
    L.y = __float2bfloat16(b - __bfloat162float(hb));
    hi = *reinterpret_cast<unsigned*>(&H);
    lo = *reinterpret_cast<unsigned*>(&L);
}
__device__ __forceinline__ float fexp_neg(float x) {
    x = fmaxf(x, -80.0f);
    float t  = fmaf(x, 1.4426950408889634f, 12582912.0f);
    float nf = t - 12582912.0f;
    float r  = fmaf(x, 1.4426950408889634f, -nf);
    float p  =             1.5403530393381609e-4f;
    p = fmaf(p, r, 1.3333558146428443e-3f);
    p = fmaf(p, r, 9.6181291076284772e-3f);
    p = fmaf(p, r, 5.5504108664821580e-2f);
    p = fmaf(p, r, 2.4022650695910071e-1f);
    p = fmaf(p, r, 6.9314718055994531e-1f);
    p = fmaf(p, r, 1.0f);
    int ni = __float_as_int(t) - 0x4B400000;
    return __int_as_float(__float_as_int(p) + (ni << 23));
}

// ---------------------------------------------------------------------------
// Split fp32 -> (hi, lo) bf16 arrays.
// ---------------------------------------------------------------------------
__global__ __launch_bounds__(256) void split_bf16(
    const float* __restrict__ x,
    __nv_bfloat16* __restrict__ hi, __nv_bfloat16* __restrict__ lo, int n4)
{
    int i = blockIdx.x * 256 + threadIdx.x;
    if (i >= n4) return;
    float4 v = ((const float4*)x)[i];
    unsigned h01, l01, h23, l23;
    split2(v.x, v.y, h01, l01);
    split2(v.z, v.w, h23, l23);
    ((uint2*)hi)[i] = make_uint2(h01, h23);
    ((uint2*)lo)[i] = make_uint2(l01, l23);
}

// ---------------------------------------------------------------------------
// Tensor-core NT GEMM, 3-term bf16 split, cp.async 2-stage pipeline.
// Block tile 256x128x64, 512 threads (16 warps, warp tile 32x64).
// 1536 mma/CTA between syncs (4x R6) — matches flash's sync amortization.
// smem: per stage Ah/Al[256][72] + Bh/Bl[128][72] bf16 = 110592 B; x2 stages.
// ---------------------------------------------------------------------------
#define BM2 256
#define BN2 128
#define BK2 64
#define LDT2 72                          // bf16 units; 144B row stride, ldsm-safe
#define A_T_B (BM2 * LDT2 * 2)           // 36864 B per A tile
#define B_T_B (BN2 * LDT2 * 2)           // 18432 B per B tile
#define OFF_AH 0u
#define OFF_AL ((unsigned)A_T_B)
#define OFF_BH ((unsigned)(2 * A_T_B))
#define OFF_BL ((unsigned)(2 * A_T_B + B_T_B))
#define STAGE_B (2 * A_T_B + 2 * B_T_B)  // 110592 B
#define GSMEM2  (2 * STAGE_B)            // 221184 B

__global__ __launch_bounds__(512, 1) void gemm_bf16x3(
    const __nv_bfloat16* __restrict__ Ah, const __nv_bfloat16* __restrict__ Al,
    const __nv_bfloat16* __restrict__ Bh, const __nv_bfloat16* __restrict__ Bl,
    float* __restrict__ C, int M, int N, int K)
{
    extern __shared__ __nv_bfloat16 smem[];
    const int tid  = threadIdx.x;
    const int wid  = tid >> 5;
    const int lane = tid & 31;
    const int warpM = wid & 7;           // 0..7  (32 rows each)
    const int warpN = wid >> 3;          // 0..1  (64 cols each)
    const int mBase = blockIdx.y * BM2;
    const int nBase = blockIdx.x * BN2;

    const unsigned sbase = (unsigned)__cvta_generic_to_shared(smem);
    const int nsteps = K / BK2;          // 16

    // async-copy one stage: A 2x2048 chunks, B 2x1024 chunks (16B each)
    auto issue_stage = [&](int stage) {
        const int buf = stage & 1;
        const int k0  = stage * BK2;
        const unsigned base = sbase + (unsigned)(buf * STAGE_B);
        #pragma unroll
        for (int i = 0; i < 4; i++) {
            int idx = tid + i * 512;                 // 0..2047
            int row = idx >> 3, c16 = idx & 7;
            unsigned so = base + (unsigned)(row * LDT2) * 2 + (unsigned)c16 * 16;
            size_t g = (size_t)(mBase + row) * K + k0 + c16 * 8;
            cpa16(so + OFF_AH, &Ah[g]);
            cpa16(so + OFF_AL, &Al[g]);
        }
        #pragma unroll
        for (int i = 0; i < 2; i++) {
            int idx = tid + i * 512;                 // 0..1023
            int row = idx >> 3, c16 = idx & 7;
            unsigned so = base + (unsigned)(row * LDT2) * 2 + (unsigned)c16 * 16;
            size_t g = (size_t)(nBase + row) * K + k0 + c16 * 8;
            cpa16(so + OFF_BH, &Bh[g]);
            cpa16(so + OFF_BL, &Bl[g]);
        }
        asm volatile("cp.async.commit_group;" ::: "memory");
    };

    float acc[2][8][4];
    #pragma unroll
    for (int t = 0; t < 2; t++)
        #pragma unroll
        for (int j = 0; j < 8; j++)
            #pragma unroll
            for (int e = 0; e < 4; e++) acc[t][j][e] = 0.0f;

    issue_stage(0);
    issue_stage(1);

    for (int step = 0; step < nsteps; step++) {
        const int cur = step & 1;
        if (step + 1 < nsteps)
            asm volatile("cp.async.wait_group 1;" ::: "memory");
        else
            asm volatile("cp.async.wait_group 0;" ::: "memory");
        __syncthreads();

        const unsigned base  = sbase + (unsigned)(cur * STAGE_B);
        const unsigned aBaseH = base + OFF_AH;
        const unsigned aBaseL = base + OFF_AL;
        const unsigned bBaseH = base + OFF_BH;
        const unsigned bBaseL = base + OFF_BL;

        #pragma unroll
        for (int kk = 0; kk < BK2; kk += 16) {
            unsigned fAh[2][4], fAl[2][4];
            const int aCol = kk + ((lane >> 4) << 3);
            #pragma unroll
            for (int t = 0; t < 2; t++) {
                int aRow = warpM * 32 + t * 16 + (lane & 15);
                unsigned off = (unsigned)(aRow * LDT2 + aCol) * 2;
                ldsm_x4(fAh[t], aBaseH + off);
                ldsm_x4(fAl[t], aBaseL + off);
            }
            #pragma unroll
            for (int np = 0; np < 4; np++) {
                const int n0  = warpN * 64 + np * 16;
                const int grp = lane >> 3, r = lane & 7;
                const int bRow = n0 + ((grp & 2) << 2) + r;
                const int bCol = kk + ((grp & 1) << 3);
                unsigned boff = (unsigned)(bRow * LDT2 + bCol) * 2;
                unsigned fBh[4], fBl[4];
                ldsm_x4(fBh, bBaseH + boff);
                ldsm_x4(fBl, bBaseL + boff);
                #pragma unroll
                for (int t = 0; t < 2; t++) {
                    mma16816(acc[t][np * 2 + 0], fAh[t], fBh + 0);
                    mma16816(acc[t][np * 2 + 1], fAh[t], fBh + 2);
                    mma16816(acc[t][np * 2 + 0], fAh[t], fBl + 0);
                    mma16816(acc[t][np * 2 + 1], fAh[t], fBl + 2);
                    mma16816(acc[t][np * 2 + 0], fAl[t], fBh + 0);
                    mma16816(acc[t][np * 2 + 1], fAl[t], fBh + 2);
                }
            }
        }

        __syncthreads();                 // all warps done reading buf `cur`
        if (step + 2 < nsteps) issue_stage(step + 2);
    }

    #pragma unroll
    for (int t = 0; t < 2; t++) {
        int row = mBase + warpM * 32 + t * 16 + (lane >> 2);
        #pragma unroll
        for (int j = 0; j < 8; j++) {
            int col = nBase + warpN * 64 + j * 8 + (lane & 3) * 2;
            float2 lo2 = make_float2(acc[t][j][0], acc[t][j][1]);
            float2 hi2 = make_float2(acc[t][j][2], acc[t][j][3]);
            *(float2*)&C[(size_t)row * N + col]       = lo2;
            *(float2*)&C[(size_t)(row + 8) * N + col] = hi2;
        }
    }
}

// ---------------------------------------------------------------------------
// Row LayerNorm in place (unchanged).
// ---------------------------------------------------------------------------
__global__ __launch_bounds__(256) void ln_rows(
    float* __restrict__ X, const float* __restrict__ gamma,
    const float* __restrict__ beta)
{
    float* x = X + (size_t)blockIdx.x * EE;
    const int tid = threadIdx.x;

    float4 v = *(const float4*)&x[tid * 4];
    float s  = v.x + v.y + v.z + v.w;
    float sq = v.x * v.x + v.y * v.y + v.z * v.z + v.w * v.w;

    #pragma unroll
    for (int off = 16; off > 0; off >>= 1) {
        s  += __shfl_xor_sync(0xffffffffu, s,  off);
        sq += __shfl_xor_sync(0xffffffffu, sq, off);
    }
    __shared__ float ss[8], sqs[8];
    const int wid = tid >> 5, lane = tid & 31;
    if (lane == 0) { ss[wid] = s; sqs[wid] = sq; }
    __syncthreads();
    float ts = 0.0f, tsq = 0.0f;
    #pragma unroll
    for (int w = 0; w < 8; w++) { ts += ss[w]; tsq += sqs[w]; }

    const float inv_n = 1.0f / (float)EE;
    float mean = ts * inv_n;
    float var  = tsq * inv_n - mean * mean;
    float rstd = rsqrtf(var + 1e-5f);

    float4 g = *(const float4*)&gamma[tid * 4];
    float4 b = *(const float4*)&beta[tid * 4];
    v.x = (v.x - mean) * rstd * g.x + b.x;
    v.y = (v.y - mean) * rstd * g.y + b.y;
    v.z = (v.z - mean) * rstd * g.z + b.z;
    v.w = (v.w - mean) * rstd * g.w + b.w;
    *(float4*)&x[tid * 4] = v;
}

// ---------------------------------------------------------------------------
// Tensor-core flash attention (unchanged from R4 — verified).
// ---------------------------------------------------------------------------
#define FLQ 72

__global__ __launch_bounds__(256, 2) void flash_tc(
    const float* __restrict__ Q, const float* __restrict__ K,
    const float* __restrict__ V, float* __restrict__ O)
{
    extern __shared__ __nv_bfloat16 fsm[];
    __nv_bfloat16* Qh = fsm;
    __nv_bfloat16* Ql = Qh + 128 * FLQ;
    __nv_bfloat16* Kh = Ql + 128 * FLQ;
    __nv_bfloat16* Kl = Kh + 64 * FLQ;
    __nv_bfloat16* Vh = Kl + 64 * FLQ;
    __nv_bfloat16* Vl = Vh + 64 * FLQ;

    const int b   = blockIdx.z;
    const int h   = blockIdx.y;
    const int q0  = blockIdx.x * 128;
    const int tid = threadIdx.x;
    const int w   = tid >> 5;
    const int lane = tid & 31;
    const size_t headOff = (size_t)h * DD;

    const unsigned sb = (unsigned)__cvta_generic_to_shared(fsm);
    const unsigned uQh = sb;
    const unsigned uQl = uQh + 128 * FLQ * 2;
    const unsigned uKh = uQl + 128 * FLQ * 2;
    const unsigned uKl = uKh + 64 * FLQ * 2;
    const unsigned uVh = uKl + 64 * FLQ * 2;
    const unsigned uVl = uVh + 64 * FLQ * 2;

    {
        const int r0 = tid >> 4;
        const int c  = (tid & 15) * 4;
        #pragma unroll
        for (int p = 0; p < 8; p++) {
            int r = r0 + p * 16;
            float4 v = *(const float4*)&Q[((size_t)(b * TT + q0 + r)) * EE + headOff + c];
            v.x *= 0.125f; v.y *= 0.125f; v.z *= 0.125f; v.w *= 0.125f;
            unsigned h01, l01, h23, l23;
            split2(v.x, v.y, h01, l01);
            split2(v.z, v.w, h23, l23);
            *(uint2*)&Qh[r * FLQ + c] = make_uint2(h01, h23);
            *(uint2*)&Ql[r * FLQ + c] = make_uint2(l01, l23);
        }
    }

    float m0 = -1e30f, m1 = -1e30f, l0 = 0.0f, l1 = 0.0f;
    float o[8][4];
    #pragma unroll
    for (int j = 0; j < 8; j++)
        #pragma unroll
        for (int e = 0; e < 4; e++) o[j][e] = 0.0f;

    const int aRow   = w * 16 + (lane & 15);
    const int aColOf = (lane >> 4) << 3;
    const int grp = lane >> 3, rr = lane & 7;
    const int bRowOf = ((grp & 2) << 2) + rr;
    const int bColOf = (grp & 1) << 3;

    for (int kv0 = 0; kv0 < TT; kv0 += 64) {
        __syncthreads();
        {
            const int r0 = tid >> 4;
            const int c  = (tid & 15) * 4;
            #pragma unroll
            for (int p = 0; p < 4; p++) {
                int r = r0 + p * 16;
                size_t gidx = ((size_t)(b * TT + kv0 + r)) * EE + headOff + c;
                float4 kv = *(const float4*)&K[gidx];
                unsigned h01, l01, h23, l23;
                split2(kv.x, kv.y, h01, l01);
                split2(kv.z, kv.w, h23, l23);
                *(uint2*)&Kh[r * FLQ + c] = make_uint2(h01, h23);
                *(uint2*)&Kl[r * FLQ + c] = make_uint2(l01, l23);

                float4 vv = *(const float4*)&V[gidx];
                float ve[4] = {vv.x, vv.y, vv.z, vv.w};
                #pragma unroll
                for (int i = 0; i < 4; i++) {
                    __nv_bfloat16 hh = __float2bfloat16(ve[i]);
                    Vh[(c + i) * FLQ + r] = hh;
                    Vl[(c + i) * FLQ + r] = __float2bfloat16(ve[i] - __bfloat162float(hh));
                }
            }
        }
        __syncthreads();

        float s[8][4];
        #pragma unroll
        for (int j = 0; j < 8; j++)
            #pragma unroll
            for (int e = 0; e < 4; e++) s[j][e] = 0.0f;

        #pragma unroll
        for (int t = 0; t < 4; t++) {
            unsigned aQh[4], aQl[4];
            unsigned aoff = (unsigned)(aRow * FLQ + t * 16 + aColOf) * 2;
            ldsm_x4(aQh, uQh + aoff);
            ldsm_x4(aQl, uQl + aoff);
            #pragma unroll
            for (int j = 0; j < 4; j++) {
                unsigned boff = (unsigned)((j * 16 + bRowOf) * FLQ + t * 16 + bColOf) * 2;
                unsigned fKh[4], fKl[4];
                ldsm_x4(fKh, uKh + boff);
                ldsm_x4(fKl, uKl + boff);
                mma16816(s[2 * j + 0], aQh, fKh + 0);
                mma16816(s[2 * j + 1], aQh, fKh + 2);
                mma16816(s[2 * j + 0], aQh, fKl + 0);
                mma16816(s[2 * j + 1], aQh, fKl + 2);
                mma16816(s[2 * j + 0], aQl, fKh + 0);
                mma16816(s[2 * j + 1], aQl, fKh + 2);
            }
        }

        float mx0 = -1e30f, mx1 = -1e30f;
        #pragma unroll
        for (int j = 0; j < 8; j++) {
            mx0 = fmaxf(mx0, fmaxf(s[j][0], s[j][1]));
            mx1 = fmaxf(mx1, fmaxf(s[j][2], s[j][3]));
        }
        mx0 = fmaxf(mx0, __shfl_xor_sync(0xffffffffu, mx0, 1));
        mx0 = fmaxf(mx0, __shfl_xor_sync(0xffffffffu, mx0, 2));
        mx1 = fmaxf(mx1, __shfl_xor_sync(0xffffffffu, mx1, 1));
        mx1 = fmaxf(mx1, __shfl_xor_sync(0xffffffffu, mx1, 2));

        float mn0 = fmaxf(m0, mx0), mn1 = fmaxf(m1, mx1);
        float c0 = fexp_neg(m0 - mn0), c1 = fexp_neg(m1 - mn1);
        m0 = mn0; m1 = mn1;

        float rs0 = 0.0f, rs1 = 0.0f;
        #pragma unroll
        for (int j = 0; j < 8; j++) {
            s[j][0] = fexp_neg(s[j][0] - mn0); rs0 += s[j][0];
            s[j][1] = fexp_neg(s[j][1] - mn0); rs0 += s[j][1];
            s[j][2] = fexp_neg(s[j][2] - mn1); rs1 += s[j][2];
            s[j][3] = fexp_neg(s[j][3] - mn1); rs1 += s[j][3];
        }
        rs0 += __shfl_xor_sync(0xffffffffu, rs0, 1);
        rs0 += __shfl_xor_sync(0xffffffffu, rs0, 2);
        rs1 += __shfl_xor_sync(0xffffffffu, rs1, 1);
        rs1 += __shfl_xor_sync(0xffffffffu, rs1, 2);
        l0 = fmaf(l0, c0, rs0);
        l1 = fmaf(l1, c1, rs1);

        #pragma unroll
        for (int j = 0; j < 8; j++) {
            o[j][0] *= c0; o[j][1] *= c0;
            o[j][2] *= c1; o[j][3] *= c1;
        }

        #pragma unroll
        for (int t = 0; t < 4; t++) {
            unsigned aPh[4], aPl[4];
            split2(s[2 * t][0],     s[2 * t][1],     aPh[0], aPl[0]);
            split2(s[2 * t][2],     s[2 * t][3],     aPh[1], aPl[1]);
            split2(s[2 * t + 1][0], s[2 * t + 1][1], aPh[2], aPl[2]);
            split2(s[2 * t + 1][2], s[2 * t + 1][3], aPh[3], aPl[3]);
            #pragma unroll
            for (int n = 0; n < 4; n++) {
                unsigned boff = (unsigned)((n * 16 + bRowOf) * FLQ + t * 16 + bColOf) * 2;
                unsigned fVh[4], fVl[4];
                ldsm_x4(fVh, uVh + boff);
                ldsm_x4(fVl, uVl + boff);
                mma16816(o[2 * n + 0], aPh, fVh + 0);
                mma16816(o[2 * n + 1], aPh, fVh + 2);
                mma16816(o[2 * n + 0], aPh, fVl + 0);
                mma16816(o[2 * n + 1], aPh, fVl + 2);
                mma16816(o[2 * n + 0], aPl, fVh + 0);
                mma16816(o[2 * n + 1], aPl, fVh + 2);
            }
        }
    }

    float inv0 = 1.0f / l0, inv1 = 1.0f / l1;
    int row0 = b * TT + q0 + w * 16 + (lane >> 2);
    #pragma unroll
    for (int j = 0; j < 8; j++) {
        size_t col = headOff + j * 8 + (lane & 3) * 2;
        *(float2*)&O[(size_t)row0 * EE + col] =
            make_float2(o[j][0] * inv0, o[j][1] * inv0);
        *(float2*)&O[(size_t)(row0 + 8) * EE + col] =
            make_float2(o[j][2] * inv1, o[j][3] * inv1);
    }
}

// ---------------------------------------------------------------------------
// Launch
// ---------------------------------------------------------------------------
extern "C" void kernel_launch(void* const* d_in, const int* in_sizes, int n_in,
                              void* d_out, int out_size)
{
    const float* xq  = (const float*)d_in[0];
    const float* xkv = (const float*)d_in[1];
    const float* W[4] = { (const float*)d_in[2], (const float*)d_in[3],
                          (const float*)d_in[4], (const float*)d_in[5] };
    const float* qg  = (const float*)d_in[6];
    const float* qb  = (const float*)d_in[7];
    const float* kg  = (const float*)d_in[8];
    const float* kb  = (const float*)d_in[9];

    float *q, *k, *v, *ctx;
    __nv_bfloat16 *ahi, *alo, *whi, *wlo;
    cudaGetSymbolAddress((void**)&q,   g_q);
    cudaGetSymbolAddress((void**)&k,   g_k);
    cudaGetSymbolAddress((void**)&v,   g_v);
    cudaGetSymbolAddress((void**)&ctx, g_ctx);
    cudaGetSymbolAddress((void**)&ahi, g_ahi);
    cudaGetSymbolAddress((void**)&alo, g_alo);
    cudaGetSymbolAddress((void**)&whi, g_whi);
    cudaGetSymbolAddress((void**)&wlo, g_wlo);

    const size_t wsz = (size_t)EE * EE;
    const int nW4 = (int)(wsz / 4);
    const int nA4 = (int)((size_t)MROWS * EE / 4);

    int smemFlash = (2 * 128 + 4 * 64) * FLQ * 2;    // 73728 B
    cudaFuncSetAttribute((const void*)gemm_bf16x3,
                         cudaFuncAttributeMaxDynamicSharedMemorySize, GSMEM2);
    cudaFuncSetAttribute((const void*)flash_tc,
                         cudaFuncAttributeMaxDynamicSharedMemorySize, smemFlash);

    for (int i = 0; i < 4; i++)
        split_bf16<<<(nW4 + 255) / 256, 256>>>(W[i], whi + i * wsz, wlo + i * wsz, nW4);

    dim3 gGrid(EE / BN2, MROWS / BM2);   // (8, 32)

    split_bf16<<<(nA4 + 255) / 256, 256>>>(xq, ahi, alo, nA4);
    gemm_bf16x3<<<gGrid, 512, GSMEM2>>>(ahi, alo, whi + 0 * wsz, wlo + 0 * wsz,
                                        q, MROWS, EE, EE);
    split_bf16<<<(nA4 + 255) / 256, 256>>>(xkv, ahi, alo, nA4);
    gemm_bf16x3<<<gGrid, 512, GSMEM2>>>(ahi, alo, whi + 1 * wsz, wlo + 1 * wsz,
                                        k, MROWS, EE, EE);
    gemm_bf16x3<<<gGrid, 512, GSMEM2>>>(ahi, alo, whi + 2 * wsz, wlo + 2 * wsz,
                                        v, MROWS, EE, EE);

    ln_rows<<<MROWS, 256>>>(q, qg, qb);
    ln_rows<<<MROWS, 256>>>(k, kg, kb);

    flash_tc<<<dim3(TT / 128, HH, BBATCH), 256, smemFlash>>>(q, k, v, ctx);

    split_bf16<<<(nA4 + 255) / 256, 256>>>(ctx, ahi, alo, nA4);
    gemm_bf16x3<<<gGrid, 512, GSMEM2>>>(ahi, alo, whi + 3 * wsz, wlo + 3 * wsz,
                                        (float*)d_out, MROWS, EE, EE);
}

// round 11
// speedup vs baseline: 2.6938x; 1.0514x over previous
#include <cuda_runtime.h>
#include <cuda_bf16.h>
#include <math.h>

// Problem constants
#define EE   1024
#define TT   2048
#define BBATCH 4
#define HH   16
#define DD   64
#define MROWS (BBATCH * TT)   // 8192

// ---------------------------------------------------------------------------
// Scratch: __device__ globals (allocation-free per harness rules)
// ---------------------------------------------------------------------------
__device__ __align__(256) float g_q[(size_t)MROWS * EE];
__device__ __align__(256) float g_k[(size_t)MROWS * EE];
__device__ __align__(256) float g_v[(size_t)MROWS * EE];
__device__ __align__(256) __nv_bfloat16 g_ahi[(size_t)MROWS * EE];
__device__ __align__(256) __nv_bfloat16 g_alo[(size_t)MROWS * EE];
__device__ __align__(256) __nv_bfloat16 g_whi[4][(size_t)EE * EE];
__device__ __align__(256) __nv_bfloat16 g_wlo[4][(size_t)EE * EE];

// ---------------------------------------------------------------------------
// Common helpers
// ---------------------------------------------------------------------------
__device__ __forceinline__ void ldsm_x4(unsigned* r, unsigned addr) {
    asm volatile("ldmatrix.sync.aligned.m8n8.x4.shared.b16 {%0,%1,%2,%3}, [%4];\n"
                 : "=r"(r[0]), "=r"(r[1]), "=r"(r[2]), "=r"(r[3]) : "r"(addr));
}
__device__ __forceinline__ void mma16816(float* c, const unsigned* a, const unsigned* b) {
    asm volatile(
        "mma.sync.aligned.m16n8k16.row.col.f32.bf16.bf16.f32 "
        "{%0,%1,%2,%3}, {%4,%5,%6,%7}, {%8,%9}, {%0,%1,%2,%3};\n"
        : "+f"(c[0]), "+f"(c[1]), "+f"(c[2]), "+f"(c[3])
        : "r"(a[0]), "r"(a[1]), "r"(a[2]), "r"(a[3]), "r"(b[0]), "r"(b[1]));
}
__device__ __forceinline__ void cpa16(unsigned dst, const void* src) {
    asm volatile("cp.async.cg.shared.global [%0], [%1], 16;"
                 :: "r"(dst), "l"(src) : "memory");
}
__device__ __forceinline__ void split2(float a, float b, unsigned& hi, unsigned& lo) {
    __nv_bfloat16 ha = __float2bfloat16(a), hb = __float2bfloat16(b);
    __nv_bfloat162 H; H.x = ha; H.y = hb;
    __nv_bfloat162 L;
    L.x = __float2bfloat16(a - __bfloat162float(ha));
    L.y = __float2bfloat16(b - __bfloat162float(hb));
    hi = *reinterpret_cast<unsigned*>(&H);
    lo = *reinterpret_cast<unsigned*>(&L);
}
__device__ __forceinline__ float fexp_neg(float x) {
    x = fmaxf(x, -80.0f);
    float t  = fmaf(x, 1.4426950408889634f, 12582912.0f);
    float nf = t - 12582912.0f;
    float r  = fmaf(x, 1.4426950408889634f, -nf);
    float p  =             1.5403530393381609e-4f;
    p = fmaf(p, r, 1.3333558146428443e-3f);
    p = fmaf(p, r, 9.6181291076284772e-3f);
    p = fmaf(p, r, 5.5504108664821580e-2f);
    p = fmaf(p, r, 2.4022650695910071e-1f);
    p = fmaf(p, r, 6.9314718055994531e-1f);
    p = fmaf(p, r, 1.0f);
    int ni = __float_as_int(t) - 0x4B400000;
    return __int_as_float(__float_as_int(p) + (ni << 23));
}

// ---------------------------------------------------------------------------
// Split fp32 -> (hi, lo) bf16 arrays.
// ---------------------------------------------------------------------------
__global__ __launch_bounds__(256) void split_bf16(
    const float* __restrict__ x,
    __nv_bfloat16* __restrict__ hi, __nv_bfloat16* __restrict__ lo, int n4)
{
    int i = blockIdx.x * 256 + threadIdx.x;
    if (i >= n4) return;
    float4 v = ((const float4*)x)[i];
    unsigned h01, l01, h23, l23;
    split2(v.x, v.y, h01, l01);
    split2(v.z, v.w, h23, l23);
    ((uint2*)hi)[i] = make_uint2(h01, h23);
    ((uint2*)lo)[i] = make_uint2(l01, l23);
}

// ---------------------------------------------------------------------------
// Tensor-core NT GEMM, 3-term bf16 split.
// Block tile 256x128x32, 512 threads (16 warps, warp tile 32x64).
// 3-stage cp.async ring; loads for stage s+2 are INTERLEAVED into stage s's
// compute (A after kk0, B+commit after kk1) to keep the L1tex wavefront
// queue shallow so ldsm completions aren't stuck behind LDGSTS bursts.
// ---------------------------------------------------------------------------
#define BM2 256
#define BN2 128
#define BK2 32
#define LDT2 40                          // bf16 units; 80B rows, ldsm conflict-free
#define A_T_B (BM2 * LDT2 * 2)           // 20480 B per A tile (hi or lo)
#define B_T_B (BN2 * LDT2 * 2)           // 10240 B per B tile
#define OFF_AH 0u
#define OFF_AL ((unsigned)A_T_B)
#define OFF_BH ((unsigned)(2 * A_T_B))
#define OFF_BL ((unsigned)(2 * A_T_B + B_T_B))
#define STAGE_B (2 * A_T_B + 2 * B_T_B)  // 61440 B
#define NSTG 3
#define GSMEM2 (NSTG * STAGE_B)          // 184320 B

__global__ __launch_bounds__(512, 1) void gemm_bf16x3(
    const __nv_bfloat16* __restrict__ Ah, const __nv_bfloat16* __restrict__ Al,
    const __nv_bfloat16* __restrict__ Bh, const __nv_bfloat16* __restrict__ Bl,
    float* __restrict__ C, int M, int N, int K)
{
    extern __shared__ __nv_bfloat16 smem[];
    const int tid  = threadIdx.x;
    const int wid  = tid >> 5;
    const int lane = tid & 31;
    const int warpM = wid & 7;           // 0..7  (32 rows each)
    const int warpN = wid >> 3;          // 0..1  (64 cols each)
    const int mBase = blockIdx.y * BM2;
    const int nBase = blockIdx.x * BN2;

    const unsigned sbase = (unsigned)__cvta_generic_to_shared(smem);
    const int nsteps = K / BK2;          // 32

    // A loads for one stage: 1024 16B-chunks (x2 hi/lo), 2 iters of 512 threads
    auto issue_A = [&](int stage) {
        const int buf = stage % NSTG;
        const int k0  = stage * BK2;
        const unsigned base = sbase + (unsigned)(buf * STAGE_B);
        #pragma unroll
        for (int i = 0; i < 2; i++) {
            int idx = tid + i * 512;                 // 0..1023
            int row = idx >> 2, c16 = idx & 3;
            unsigned so = base + (unsigned)(row * LDT2) * 2 + (unsigned)c16 * 16;
            size_t g = (size_t)(mBase + row) * K + k0 + c16 * 8;
            cpa16(so + OFF_AH, &Ah[g]);
            cpa16(so + OFF_AL, &Al[g]);
        }
    };
    // B loads for one stage: 512 16B-chunks (x2 hi/lo), 1 iter
    auto issue_B = [&](int stage) {
        const int buf = stage % NSTG;
        const int k0  = stage * BK2;
        const unsigned base = sbase + (unsigned)(buf * STAGE_B);
        int row = tid >> 2, c16 = tid & 3;           // 128 rows x 4 chunks
        unsigned so = base + (unsigned)(row * LDT2) * 2 + (unsigned)c16 * 16;
        size_t g = (size_t)(nBase + row) * K + k0 + c16 * 8;
        cpa16(so + OFF_BH, &Bh[g]);
        cpa16(so + OFF_BL, &Bl[g]);
    };

    float acc[2][8][4];
    #pragma unroll
    for (int t = 0; t < 2; t++)
        #pragma unroll
        for (int j = 0; j < 8; j++)
            #pragma unroll
            for (int e = 0; e < 4; e++) acc[t][j][e] = 0.0f;

    // prologue: stages 0 and 1
    issue_A(0); issue_B(0);
    asm volatile("cp.async.commit_group;" ::: "memory");
    issue_A(1); issue_B(1);
    asm volatile("cp.async.commit_group;" ::: "memory");

    for (int step = 0; step < nsteps; step++) {
        const int cur = step % NSTG;
        const bool more = (step + 2 < nsteps);
        if (more)
            asm volatile("cp.async.wait_group 1;" ::: "memory");
        else
            asm volatile("cp.async.wait_group 0;" ::: "memory");
        __syncthreads();

        const unsigned base   = sbase + (unsigned)(cur * STAGE_B);
        const unsigned aBaseH = base + OFF_AH;
        const unsigned aBaseL = base + OFF_AL;
        const unsigned bBaseH = base + OFF_BH;
        const unsigned bBaseL = base + OFF_BL;

        #pragma unroll
        for (int kk = 0; kk < BK2; kk += 16) {
            unsigned fAh[2][4], fAl[2][4];
            const int aCol = kk + ((lane >> 4) << 3);
            #pragma unroll
            for (int t = 0; t < 2; t++) {
                int aRow = warpM * 32 + t * 16 + (lane & 15);
                unsigned off = (unsigned)(aRow * LDT2 + aCol) * 2;
                ldsm_x4(fAh[t], aBaseH + off);
                ldsm_x4(fAl[t], aBaseL + off);
            }
            #pragma unroll
            for (int np = 0; np < 4; np++) {
                const int n0  = warpN * 64 + np * 16;
                const int grp = lane >> 3, r = lane & 7;
                const int bRow = n0 + ((grp & 2) << 2) + r;
                const int bCol = kk + ((grp & 1) << 3);
                unsigned boff = (unsigned)(bRow * LDT2 + bCol) * 2;
                unsigned fBh[4], fBl[4];
                ldsm_x4(fBh, bBaseH + boff);
                ldsm_x4(fBl, bBaseL + boff);
                #pragma unroll
                for (int t = 0; t < 2; t++) {
                    mma16816(acc[t][np * 2 + 0], fAh[t], fBh + 0);
                    mma16816(acc[t][np * 2 + 1], fAh[t], fBh + 2);
                    mma16816(acc[t][np * 2 + 0], fAh[t], fBl + 0);
                    mma16816(acc[t][np * 2 + 1], fAh[t], fBl + 2);
                    mma16816(acc[t][np * 2 + 0], fAl[t], fBh + 0);
                    mma16816(acc[t][np * 2 + 1], fAl[t], fBh + 2);
                }
            }
            // interleave next-next stage loads (target buffer (step+2)%3 is
            // not read by stage step or step+1; prior reuse ordered by the
            // top-of-stage __syncthreads)
            if (more) {
                if (kk == 0) {
                    issue_A(step + 2);
                } else {
                    issue_B(step + 2);
                    asm volatile("cp.async.commit_group;" ::: "memory");
                }
            }
        }
    }

    #pragma unroll
    for (int t = 0; t < 2; t++) {
        int row = mBase + warpM * 32 + t * 16 + (lane >> 2);
        #pragma unroll
        for (int j = 0; j < 8; j++) {
            int col = nBase + warpN * 64 + j * 8 + (lane & 3) * 2;
            float2 lo2 = make_float2(acc[t][j][0], acc[t][j][1]);
            float2 hi2 = make_float2(acc[t][j][2], acc[t][j][3]);
            *(float2*)&C[(size_t)row * N + col]       = lo2;
            *(float2*)&C[(size_t)(row + 8) * N + col] = hi2;
        }
    }
}

// ---------------------------------------------------------------------------
// Row LayerNorm in place (unchanged).
// ---------------------------------------------------------------------------
__global__ __launch_bounds__(256) void ln_rows(
    float* __restrict__ X, const float* __restrict__ gamma,
    const float* __restrict__ beta)
{
    float* x = X + (size_t)blockIdx.x * EE;
    const int tid = threadIdx.x;

    float4 v = *(const float4*)&x[tid * 4];
    float s  = v.x + v.y + v.z + v.w;
    float sq = v.x * v.x + v.y * v.y + v.z * v.z + v.w * v.w;

    #pragma unroll
    for (int off = 16; off > 0; off >>= 1) {
        s  += __shfl_xor_sync(0xffffffffu, s,  off);
        sq += __shfl_xor_sync(0xffffffffu, sq, off);
    }
    __shared__ float ss[8], sqs[8];
    const int wid = tid >> 5, lane = tid & 31;
    if (lane == 0) { ss[wid] = s; sqs[wid] = sq; }
    __syncthreads();
    float ts = 0.0f, tsq = 0.0f;
    #pragma unroll
    for (int w = 0; w < 8; w++) { ts += ss[w]; tsq += sqs[w]; }

    const float inv_n = 1.0f / (float)EE;
    float mean = ts * inv_n;
    float var  = tsq * inv_n - mean * mean;
    float rstd = rsqrtf(var + 1e-5f);

    float4 g = *(const float4*)&gamma[tid * 4];
    float4 b = *(const float4*)&beta[tid * 4];
    v.x = (v.x - mean) * rstd * g.x + b.x;
    v.y = (v.y - mean) * rstd * g.y + b.y;
    v.z = (v.z - mean) * rstd * g.z + b.z;
    v.w = (v.w - mean) * rstd * g.w + b.w;
    *(float4*)&x[tid * 4] = v;
}

// ---------------------------------------------------------------------------
// Tensor-core flash attention. Epilogue now writes the context PRE-SPLIT
// (hi/lo bf16) so the O-projection consumes it directly — the ctx split
// kernel is gone. Values are bit-identical to split-after-fp32-roundtrip.
// ---------------------------------------------------------------------------
#define FLQ 72

__global__ __launch_bounds__(256, 2) void flash_tc(
    const float* __restrict__ Q, const float* __restrict__ K,
    const float* __restrict__ V,
    __nv_bfloat16* __restrict__ Ohi, __nv_bfloat16* __restrict__ Olo)
{
    extern __shared__ __nv_bfloat16 fsm[];
    __nv_bfloat16* Qh = fsm;
    __nv_bfloat16* Ql = Qh + 128 * FLQ;
    __nv_bfloat16* Kh = Ql + 128 * FLQ;
    __nv_bfloat16* Kl = Kh + 64 * FLQ;
    __nv_bfloat16* Vh = Kl + 64 * FLQ;
    __nv_bfloat16* Vl = Vh + 64 * FLQ;

    const int b   = blockIdx.z;
    const int h   = blockIdx.y;
    const int q0  = blockIdx.x * 128;
    const int tid = threadIdx.x;
    const int w   = tid >> 5;
    const int lane = tid & 31;
    const size_t headOff = (size_t)h * DD;

    const unsigned sb = (unsigned)__cvta_generic_to_shared(fsm);
    const unsigned uQh = sb;
    const unsigned uQl = uQh + 128 * FLQ * 2;
    const unsigned uKh = uQl + 128 * FLQ * 2;
    const unsigned uKl = uKh + 64 * FLQ * 2;
    const unsigned uVh = uKl + 64 * FLQ * 2;
    const unsigned uVl = uVh + 64 * FLQ * 2;

    {
        const int r0 = tid >> 4;
        const int c  = (tid & 15) * 4;
        #pragma unroll
        for (int p = 0; p < 8; p++) {
            int r = r0 + p * 16;
            float4 v = *(const float4*)&Q[((size_t)(b * TT + q0 + r)) * EE + headOff + c];
            v.x *= 0.125f; v.y *= 0.125f; v.z *= 0.125f; v.w *= 0.125f;
            unsigned h01, l01, h23, l23;
            split2(v.x, v.y, h01, l01);
            split2(v.z, v.w, h23, l23);
            *(uint2*)&Qh[r * FLQ + c] = make_uint2(h01, h23);
            *(uint2*)&Ql[r * FLQ + c] = make_uint2(l01, l23);
        }
    }

    float m0 = -1e30f, m1 = -1e30f, l0 = 0.0f, l1 = 0.0f;
    float o[8][4];
    #pragma unroll
    for (int j = 0; j < 8; j++)
        #pragma unroll
        for (int e = 0; e < 4; e++) o[j][e] = 0.0f;

    const int aRow   = w * 16 + (lane & 15);
    const int aColOf = (lane >> 4) << 3;
    const int grp = lane >> 3, rr = lane & 7;
    const int bRowOf = ((grp & 2) << 2) + rr;
    const int bColOf = (grp & 1) << 3;

    for (int kv0 = 0; kv0 < TT; kv0 += 64) {
        __syncthreads();
        {
            const int r0 = tid >> 4;
            const int c  = (tid & 15) * 4;
            #pragma unroll
            for (int p = 0; p < 4; p++) {
                int r = r0 + p * 16;
                size_t gidx = ((size_t)(b * TT + kv0 + r)) * EE + headOff + c;
                float4 kv = *(const float4*)&K[gidx];
                unsigned h01, l01, h23, l23;
                split2(kv.x, kv.y, h01, l01);
                split2(kv.z, kv.w, h23, l23);
                *(uint2*)&Kh[r * FLQ + c] = make_uint2(h01, h23);
                *(uint2*)&Kl[r * FLQ + c] = make_uint2(l01, l23);

                float4 vv = *(const float4*)&V[gidx];
                float ve[4] = {vv.x, vv.y, vv.z, vv.w};
                #pragma unroll
                for (int i = 0; i < 4; i++) {
                    __nv_bfloat16 hh = __float2bfloat16(ve[i]);
                    Vh[(c + i) * FLQ + r] = hh;
                    Vl[(c + i) * FLQ + r] = __float2bfloat16(ve[i] - __bfloat162float(hh));
                }
            }
        }
        __syncthreads();

        float s[8][4];
        #pragma unroll
        for (int j = 0; j < 8; j++)
            #pragma unroll
            for (int e = 0; e < 4; e++) s[j][e] = 0.0f;

        #pragma unroll
        for (int t = 0; t < 4; t++) {
            unsigned aQh[4], aQl[4];
            unsigned aoff = (unsigned)(aRow * FLQ + t * 16 + aColOf) * 2;
            ldsm_x4(aQh, uQh + aoff);
            ldsm_x4(aQl, uQl + aoff);
            #pragma unroll
            for (int j = 0; j < 4; j++) {
                unsigned boff = (unsigned)((j * 16 + bRowOf) * FLQ + t * 16 + bColOf) * 2;
                unsigned fKh[4], fKl[4];
                ldsm_x4(fKh, uKh + boff);
                ldsm_x4(fKl, uKl + boff);
                mma16816(s[2 * j + 0], aQh, fKh + 0);
                mma16816(s[2 * j + 1], aQh, fKh + 2);
                mma16816(s[2 * j + 0], aQh, fKl + 0);
                mma16816(s[2 * j + 1], aQh, fKl + 2);
                mma16816(s[2 * j + 0], aQl, fKh + 0);
                mma16816(s[2 * j + 1], aQl, fKh + 2);
            }
        }

        float mx0 = -1e30f, mx1 = -1e30f;
        #pragma unroll
        for (int j = 0; j < 8; j++) {
            mx0 = fmaxf(mx0, fmaxf(s[j][0], s[j][1]));
            mx1 = fmaxf(mx1, fmaxf(s[j][2], s[j][3]));
        }
        mx0 = fmaxf(mx0, __shfl_xor_sync(0xffffffffu, mx0, 1));
        mx0 = fmaxf(mx0, __shfl_xor_sync(0xffffffffu, mx0, 2));
        mx1 = fmaxf(mx1, __shfl_xor_sync(0xffffffffu, mx1, 1));
        mx1 = fmaxf(mx1, __shfl_xor_sync(0xffffffffu, mx1, 2));

        float mn0 = fmaxf(m0, mx0), mn1 = fmaxf(m1, mx1);
        float c0 = fexp_neg(m0 - mn0), c1 = fexp_neg(m1 - mn1);
        m0 = mn0; m1 = mn1;

        float rs0 = 0.0f, rs1 = 0.0f;
        #pragma unroll
        for (int j = 0; j < 8; j++) {
            s[j][0] = fexp_neg(s[j][0] - mn0); rs0 += s[j][0];
            s[j][1] = fexp_neg(s[j][1] - mn0); rs0 += s[j][1];
            s[j][2] = fexp_neg(s[j][2] - mn1); rs1 += s[j][2];
            s[j][3] = fexp_neg(s[j][3] - mn1); rs1 += s[j][3];
        }
        rs0 += __shfl_xor_sync(0xffffffffu, rs0, 1);
        rs0 += __shfl_xor_sync(0xffffffffu, rs0, 2);
        rs1 += __shfl_xor_sync(0xffffffffu, rs1, 1);
        rs1 += __shfl_xor_sync(0xffffffffu, rs1, 2);
        l0 = fmaf(l0, c0, rs0);
        l1 = fmaf(l1, c1, rs1);

        #pragma unroll
        for (int j = 0; j < 8; j++) {
            o[j][0] *= c0; o[j][1] *= c0;
            o[j][2] *= c1; o[j][3] *= c1;
        }

        #pragma unroll
        for (int t = 0; t < 4; t++) {
            unsigned aPh[4], aPl[4];
            split2(s[2 * t][0],     s[2 * t][1],     aPh[0], aPl[0]);
            split2(s[2 * t][2],     s[2 * t][3],     aPh[1], aPl[1]);
            split2(s[2 * t + 1][0], s[2 * t + 1][1], aPh[2], aPl[2]);
            split2(s[2 * t + 1][2], s[2 * t + 1][3], aPh[3], aPl[3]);
            #pragma unroll
            for (int n = 0; n < 4; n++) {
                unsigned boff = (unsigned)((n * 16 + bRowOf) * FLQ + t * 16 + bColOf) * 2;
                unsigned fVh[4], fVl[4];
                ldsm_x4(fVh, uVh + boff);
                ldsm_x4(fVl, uVl + boff);
                mma16816(o[2 * n + 0], aPh, fVh + 0);
                mma16816(o[2 * n + 1], aPh, fVh + 2);
                mma16816(o[2 * n + 0], aPh, fVl + 0);
                mma16816(o[2 * n + 1], aPh, fVl + 2);
                mma16816(o[2 * n + 0], aPl, fVh + 0);
                mma16816(o[2 * n + 1], aPl, fVh + 2);
            }
        }
    }

    // epilogue: normalize and store PRE-SPLIT hi/lo bf16
    float inv0 = 1.0f / l0, inv1 = 1.0f / l1;
    int row0 = b * TT + q0 + w * 16 + (lane >> 2);
    #pragma unroll
    for (int j = 0; j < 8; j++) {
        size_t col = headOff + j * 8 + (lane & 3) * 2;
        unsigned h0, l0u, h1, l1u;
        split2(o[j][0] * inv0, o[j][1] * inv0, h0, l0u);
        split2(o[j][2] * inv1, o[j][3] * inv1, h1, l1u);
        *(unsigned*)&Ohi[(size_t)row0 * EE + col]       = h0;
        *(unsigned*)&Olo[(size_t)row0 * EE + col]       = l0u;
        *(unsigned*)&Ohi[(size_t)(row0 + 8) * EE + col] = h1;
        *(unsigned*)&Olo[(size_t)(row0 + 8) * EE + col] = l1u;
    }
}

// ---------------------------------------------------------------------------
// Launch
// ---------------------------------------------------------------------------
extern "C" void kernel_launch(void* const* d_in, const int* in_sizes, int n_in,
                              void* d_out, int out_size)
{
    const float* xq  = (const float*)d_in[0];
    const float* xkv = (const float*)d_in[1];
    const float* W[4] = { (const float*)d_in[2], (const float*)d_in[3],
                          (const float*)d_in[4], (const float*)d_in[5] };
    const float* qg  = (const float*)d_in[6];
    const float* qb  = (const float*)d_in[7];
    const float* kg  = (const float*)d_in[8];
    const float* kb  = (const float*)d_in[9];

    float *q, *k, *v;
    __nv_bfloat16 *ahi, *alo, *whi, *wlo;
    cudaGetSymbolAddress((void**)&q,   g_q);
    cudaGetSymbolAddress((void**)&k,   g_k);
    cudaGetSymbolAddress((void**)&v,   g_v);
    cudaGetSymbolAddress((void**)&ahi, g_ahi);
    cudaGetSymbolAddress((void**)&alo, g_alo);
    cudaGetSymbolAddress((void**)&whi, g_whi);
    cudaGetSymbolAddress((void**)&wlo, g_wlo);

    const size_t wsz = (size_t)EE * EE;
    const int nW4 = (int)(wsz / 4);
    const int nA4 = (int)((size_t)MROWS * EE / 4);

    int smemFlash = (2 * 128 + 4 * 64) * FLQ * 2;    // 73728 B
    cudaFuncSetAttribute((const void*)gemm_bf16x3,
                         cudaFuncAttributeMaxDynamicSharedMemorySize, GSMEM2);
    cudaFuncSetAttribute((const void*)flash_tc,
                         cudaFuncAttributeMaxDynamicSharedMemorySize, smemFlash);

    for (int i = 0; i < 4; i++)
        split_bf16<<<(nW4 + 255) / 256, 256>>>(W[i], whi + i * wsz, wlo + i * wsz, nW4);

    dim3 gGrid(EE / BN2, MROWS / BM2);   // (8, 32)

    split_bf16<<<(nA4 + 255) / 256, 256>>>(xq, ahi, alo, nA4);
    gemm_bf16x3<<<gGrid, 512, GSMEM2>>>(ahi, alo, whi + 0 * wsz, wlo + 0 * wsz,
                                        q, MROWS, EE, EE);
    split_bf16<<<(nA4 + 255) / 256, 256>>>(xkv, ahi, alo, nA4);
    gemm_bf16x3<<<gGrid, 512, GSMEM2>>>(ahi, alo, whi + 1 * wsz, wlo + 1 * wsz,
                                        k, MROWS, EE, EE);
    gemm_bf16x3<<<gGrid, 512, GSMEM2>>>(ahi, alo, whi + 2 * wsz, wlo + 2 * wsz,
                                        v, MROWS, EE, EE);

    ln_rows<<<MROWS, 256>>>(q, qg, qb);
    ln_rows<<<MROWS, 256>>>(k, kg, kb);

    // flash writes the context pre-split into ahi/alo (already consumed by
    // the K/V projections above), feeding the O projection directly.
    flash_tc<<<dim3(TT / 128, HH, BBATCH), 256, smemFlash>>>(q, k, v, ahi, alo);

    gemm_bf16x3<<<gGrid, 512, GSMEM2>>>(ahi, alo, whi + 3 * wsz, wlo + 3 * wsz,
                                        (float*)d_out, MROWS, EE, EE);
}

// round 13
// speedup vs baseline: 2.7525x; 1.0218x over previous
#include <cuda_runtime.h>
#include <cuda_bf16.h>
#include <math.h>

// Problem constants
#define EE   1024
#define TT   2048
#define BBATCH 4
#define HH   16
#define DD   64
#define MROWS (BBATCH * TT)   // 8192

// ---------------------------------------------------------------------------
// Scratch: __device__ globals (allocation-free per harness rules)
// ---------------------------------------------------------------------------
__device__ __align__(256) float g_q[(size_t)MROWS * EE];
__device__ __align__(256) float g_k[(size_t)MROWS * EE];
__device__ __align__(256) float g_v[(size_t)MROWS * EE];
__device__ __align__(256) __nv_bfloat16 g_ahi[(size_t)MROWS * EE];   // xq split, then ctx split
__device__ __align__(256) __nv_bfloat16 g_alo[(size_t)MROWS * EE];
__device__ __align__(256) __nv_bfloat16 g_kvhi[(size_t)MROWS * EE];  // xkv split
__device__ __align__(256) __nv_bfloat16 g_kvlo[(size_t)MROWS * EE];
__device__ __align__(256) __nv_bfloat16 g_whi[4][(size_t)EE * EE];
__device__ __align__(256) __nv_bfloat16 g_wlo[4][(size_t)EE * EE];

// ---------------------------------------------------------------------------
// Common helpers
// ---------------------------------------------------------------------------
__device__ __forceinline__ void ldsm_x4(unsigned* r, unsigned addr) {
    asm volatile("ldmatrix.sync.aligned.m8n8.x4.shared.b16 {%0,%1,%2,%3}, [%4];\n"
                 : "=r"(r[0]), "=r"(r[1]), "=r"(r[2]), "=r"(r[3]) : "r"(addr));
}
__device__ __forceinline__ void mma16816(float* c, const unsigned* a, const unsigned* b) {
    asm volatile(
        "mma.sync.aligned.m16n8k16.row.col.f32.bf16.bf16.f32 "
        "{%0,%1,%2,%3}, {%4,%5,%6,%7}, {%8,%9}, {%0,%1,%2,%3};\n"
        : "+f"(c[0]), "+f"(c[1]), "+f"(c[2]), "+f"(c[3])
        : "r"(a[0]), "r"(a[1]), "r"(a[2]), "r"(a[3]), "r"(b[0]), "r"(b[1]));
}
__device__ __forceinline__ void cpa16(unsigned dst, const void* src) {
    asm volatile("cp.async.cg.shared.global [%0], [%1], 16;"
                 :: "r"(dst), "l"(src) : "memory");
}
__device__ __forceinline__ void split2(float a, float b, unsigned& hi, unsigned& lo) {
    __nv_bfloat16 ha = __float2bfloat16(a), hb = __float2bfloat16(b);
    __nv_bfloat162 H; H.x = ha; H.y = hb;
    __nv_bfloat162 L;
    L.x = __float2bfloat16(a - __bfloat162float(ha));
    L.y = __float2bfloat16(b - __bfloat162float(hb));
    hi = *reinterpret_cast<unsigned*>(&H);
    lo = *reinterpret_cast<unsigned*>(&L);
}
__device__ __forceinline__ float fexp_neg(float x) {
    x = fmaxf(x, -80.0f);
    float t  = fmaf(x, 1.4426950408889634f, 12582912.0f);
    float nf = t - 12582912.0f;
    float r  = fmaf(x, 1.4426950408889634f, -nf);
    float p  =             1.5403530393381609e-4f;
    p = fmaf(p, r, 1.3333558146428443e-3f);
    p = fmaf(p, r, 9.6181291076284772e-3f);
    p = fmaf(p, r, 5.5504108664821580e-2f);
    p = fmaf(p, r, 2.4022650695910071e-1f);
    p = fmaf(p, r, 6.9314718055994531e-1f);
    p = fmaf(p, r, 1.0f);
    int ni = __float_as_int(t) - 0x4B400000;
    return __int_as_float(__float_as_int(p) + (ni << 23));
}

// ---------------------------------------------------------------------------
// Split fp32 -> (hi, lo) bf16 arrays.
// ---------------------------------------------------------------------------
__global__ __launch_bounds__(256) void split_bf16(
    const float* __restrict__ x,
    __nv_bfloat16* __restrict__ hi, __nv_bfloat16* __restrict__ lo, int n4)
{
    int i = blockIdx.x * 256 + threadIdx.x;
    if (i >= n4) return;
    float4 v = ((const float4*)x)[i];
    unsigned h01, l01, h23, l23;
    split2(v.x, v.y, h01, l01);
    split2(v.z, v.w, h23, l23);
    ((uint2*)hi)[i] = make_uint2(h01, h23);
    ((uint2*)lo)[i] = make_uint2(l01, l23);
}

// ---------------------------------------------------------------------------
// Tensor-core NT GEMM, 3-term bf16 split. Fused multi-head variant:
// blockIdx.z selects (A pair, weight slab bOff+z, C target).
// Block tile 128x128x32, 256 threads (8 warps, warp tile 32x64).
// 2-stage cp.async ring, ONE commit per stage, loads for stage s+1
// interleaved into stage s's compute. wait_group 0 at the top of each
// step drains exactly the stage about to be read (only one group is ever
// pending there — R12's NaN came from wait_group 1 being a no-op here).
// __launch_bounds__(256,2): 2 CTAs/SM (2x81920B smem = 160KB) so one CTA's
// wait/barrier holes are filled by the other.
// ---------------------------------------------------------------------------
#define BM3 128
#define BN3 128
#define BK3 32
#define LDT3 40                          // bf16 units; 80B rows, ldsm conflict-free
#define A3_B (BM3 * LDT3 * 2)            // 10240 B per A tile (hi or lo)
#define B3_B (BN3 * LDT3 * 2)            // 10240 B per B tile
#define OFF3_AH 0u
#define OFF3_AL ((unsigned)A3_B)
#define OFF3_BH ((unsigned)(2 * A3_B))
#define OFF3_BL ((unsigned)(2 * A3_B + B3_B))
#define STAGE3 (2 * A3_B + 2 * B3_B)     // 40960 B
#define NSTG3 2
#define GSMEM3 (NSTG3 * STAGE3)          // 81920 B per CTA; x2 CTAs = 160KB

__global__ __launch_bounds__(256, 2) void gemm_bf16x3(
    const __nv_bfloat16* __restrict__ A0h, const __nv_bfloat16* __restrict__ A0l,
    const __nv_bfloat16* __restrict__ A1h, const __nv_bfloat16* __restrict__ A1l,
    const __nv_bfloat16* __restrict__ WhB, const __nv_bfloat16* __restrict__ WlB,
    float* __restrict__ C0, float* __restrict__ C1, float* __restrict__ C2,
    int bOff, int M, int N, int K)
{
    extern __shared__ __nv_bfloat16 smem[];
    const int tid  = threadIdx.x;
    const int wid  = tid >> 5;
    const int lane = tid & 31;
    const int warpM = wid & 3;           // 0..3  (32 rows each)
    const int warpN = wid >> 2;          // 0..1  (64 cols each)
    const int mBase = blockIdx.y * BM3;
    const int nBase = blockIdx.x * BN3;
    const int z     = blockIdx.z;

    const __nv_bfloat16* Ah = (z == 0) ? A0h : A1h;
    const __nv_bfloat16* Al = (z == 0) ? A0l : A1l;
    const size_t wsz = (size_t)EE * EE;
    const __nv_bfloat16* Bh = WhB + (size_t)(bOff + z) * wsz;
    const __nv_bfloat16* Bl = WlB + (size_t)(bOff + z) * wsz;
    float* C = (z == 0) ? C0 : ((z == 1) ? C1 : C2);

    const unsigned sbase = (unsigned)__cvta_generic_to_shared(smem);
    const int nsteps = K / BK3;          // 32

    // A loads: 512 chunks x2(hi/lo) over 2 iters of 256 threads
    auto issue_A = [&](int stage) {
        const int buf = stage & 1;
        const int k0  = stage * BK3;
        const unsigned base = sbase + (unsigned)(buf * STAGE3);
        #pragma unroll
        for (int i = 0; i < 2; i++) {
            int idx = tid + i * 256;                 // 0..511
            int row = idx >> 2, c16 = idx & 3;
            unsigned so = base + (unsigned)(row * LDT3) * 2 + (unsigned)c16 * 16;
            size_t g = (size_t)(mBase + row) * K + k0 + c16 * 8;
            cpa16(so + OFF3_AH, &Ah[g]);
            cpa16(so + OFF3_AL, &Al[g]);
        }
    };
    auto issue_B = [&](int stage) {
        const int buf = stage & 1;
        const int k0  = stage * BK3;
        const unsigned base = sbase + (unsigned)(buf * STAGE3);
        #pragma unroll
        for (int i = 0; i < 2; i++) {
            int idx = tid + i * 256;                 // 0..511
            int row = idx >> 2, c16 = idx & 3;
            unsigned so = base + (unsigned)(row * LDT3) * 2 + (unsigned)c16 * 16;
            size_t g = (size_t)(nBase + row) * K + k0 + c16 * 8;
            cpa16(so + OFF3_BH, &Bh[g]);
            cpa16(so + OFF3_BL, &Bl[g]);
        }
    };

    float acc[2][8][4];
    #pragma unroll
    for (int t = 0; t < 2; t++)
        #pragma unroll
        for (int j = 0; j < 8; j++)
            #pragma unroll
            for (int e = 0; e < 4; e++) acc[t][j][e] = 0.0f;

    // prologue: stage 0 committed (one group)
    issue_A(0); issue_B(0);
    asm volatile("cp.async.commit_group;" ::: "memory");

    for (int step = 0; step < nsteps; step++) {
        const int cur = step & 1;
        const bool more = (step + 1 < nsteps);
        // Exactly one group (stage `step`) is pending here — drain it fully.
        asm volatile("cp.async.wait_group 0;" ::: "memory");
        __syncthreads();

        const unsigned base   = sbase + (unsigned)(cur * STAGE3);
        const unsigned aBaseH = base + OFF3_AH;
        const unsigned aBaseL = base + OFF3_AL;
        const unsigned bBaseH = base + OFF3_BH;
        const unsigned bBaseL = base + OFF3_BL;

        #pragma unroll
        for (int kk = 0; kk < BK3; kk += 16) {
            unsigned fAh[2][4], fAl[2][4];
            const int aCol = kk + ((lane >> 4) << 3);
            #pragma unroll
            for (int t = 0; t < 2; t++) {
                int aRow = warpM * 32 + t * 16 + (lane & 15);
                unsigned off = (unsigned)(aRow * LDT3 + aCol) * 2;
                ldsm_x4(fAh[t], aBaseH + off);
                ldsm_x4(fAl[t], aBaseL + off);
            }
            #pragma unroll
            for (int np = 0; np < 4; np++) {
                const int n0  = warpN * 64 + np * 16;
                const int grp = lane >> 3, r = lane & 7;
                const int bRow = n0 + ((grp & 2) << 2) + r;
                const int bCol = kk + ((grp & 1) << 3);
                unsigned boff = (unsigned)(bRow * LDT3 + bCol) * 2;
                unsigned fBh[4], fBl[4];
                ldsm_x4(fBh, bBaseH + boff);
                ldsm_x4(fBl, bBaseL + boff);
                #pragma unroll
                for (int t = 0; t < 2; t++) {
                    mma16816(acc[t][np * 2 + 0], fAh[t], fBh + 0);
                    mma16816(acc[t][np * 2 + 1], fAh[t], fBh + 2);
                    mma16816(acc[t][np * 2 + 0], fAh[t], fBl + 0);
                    mma16816(acc[t][np * 2 + 1], fAh[t], fBl + 2);
                    mma16816(acc[t][np * 2 + 0], fAl[t], fBh + 0);
                    mma16816(acc[t][np * 2 + 1], fAl[t], fBh + 2);
                }
            }
            // Interleave next stage's loads into this stage's compute.
            // Target buffer (step+1)&1 != cur; its previous contents (stage
            // step-1) were fully consumed before the top-of-stage sync.
            if (more) {
                if (kk == 0) {
                    issue_A(step + 1);
                } else {
                    issue_B(step + 1);
                    asm volatile("cp.async.commit_group;" ::: "memory");
                }
            }
        }
    }

    #pragma unroll
    for (int t = 0; t < 2; t++) {
        int row = mBase + warpM * 32 + t * 16 + (lane >> 2);
        #pragma unroll
        for (int j = 0; j < 8; j++) {
            int col = nBase + warpN * 64 + j * 8 + (lane & 3) * 2;
            float2 lo2 = make_float2(acc[t][j][0], acc[t][j][1]);
            float2 hi2 = make_float2(acc[t][j][2], acc[t][j][3]);
            *(float2*)&C[(size_t)row * N + col]       = lo2;
            *(float2*)&C[(size_t)(row + 8) * N + col] = hi2;
        }
    }
}

// ---------------------------------------------------------------------------
// Row LayerNorm in place (unchanged).
// ---------------------------------------------------------------------------
__global__ __launch_bounds__(256) void ln_rows(
    float* __restrict__ X, const float* __restrict__ gamma,
    const float* __restrict__ beta)
{
    float* x = X + (size_t)blockIdx.x * EE;
    const int tid = threadIdx.x;

    float4 v = *(const float4*)&x[tid * 4];
    float s  = v.x + v.y + v.z + v.w;
    float sq = v.x * v.x + v.y * v.y + v.z * v.z + v.w * v.w;

    #pragma unroll
    for (int off = 16; off > 0; off >>= 1) {
        s  += __shfl_xor_sync(0xffffffffu, s,  off);
        sq += __shfl_xor_sync(0xffffffffu, sq, off);
    }
    __shared__ float ss[8], sqs[8];
    const int wid = tid >> 5, lane = tid & 31;
    if (lane == 0) { ss[wid] = s; sqs[wid] = sq; }
    __syncthreads();
    float ts = 0.0f, tsq = 0.0f;
    #pragma unroll
    for (int w = 0; w < 8; w++) { ts += ss[w]; tsq += sqs[w]; }

    const float inv_n = 1.0f / (float)EE;
    float mean = ts * inv_n;
    float var  = tsq * inv_n - mean * mean;
    float rstd = rsqrtf(var + 1e-5f);

    float4 g = *(const float4*)&gamma[tid * 4];
    float4 b = *(const float4*)&beta[tid * 4];
    v.x = (v.x - mean) * rstd * g.x + b.x;
    v.y = (v.y - mean) * rstd * g.y + b.y;
    v.z = (v.z - mean) * rstd * g.z + b.z;
    v.w = (v.w - mean) * rstd * g.w + b.w;
    *(float4*)&x[tid * 4] = v;
}

// ---------------------------------------------------------------------------
// Tensor-core flash attention (unchanged — verified).
// Writes the context PRE-SPLIT (hi/lo bf16) for the O projection.
// ---------------------------------------------------------------------------
#define FLQ 72

__global__ __launch_bounds__(256, 2) void flash_tc(
    const float* __restrict__ Q, const float* __restrict__ K,
    const float* __restrict__ V,
    __nv_bfloat16* __restrict__ Ohi, __nv_bfloat16* __restrict__ Olo)
{
    extern __shared__ __nv_bfloat16 fsm[];
    __nv_bfloat16* Qh = fsm;
    __nv_bfloat16* Ql = Qh + 128 * FLQ;
    __nv_bfloat16* Kh = Ql + 128 * FLQ;
    __nv_bfloat16* Kl = Kh + 64 * FLQ;
    __nv_bfloat16* Vh = Kl + 64 * FLQ;
    __nv_bfloat16* Vl = Vh + 64 * FLQ;

    const int b   = blockIdx.z;
    const int h   = blockIdx.y;
    const int q0  = blockIdx.x * 128;
    const int tid = threadIdx.x;
    const int w   = tid >> 5;
    const int lane = tid & 31;
    const size_t headOff = (size_t)h * DD;

    const unsigned sb = (unsigned)__cvta_generic_to_shared(fsm);
    const unsigned uQh = sb;
    const unsigned uQl = uQh + 128 * FLQ * 2;
    const unsigned uKh = uQl + 128 * FLQ * 2;
    const unsigned uKl = uKh + 64 * FLQ * 2;
    const unsigned uVh = uKl + 64 * FLQ * 2;
    const unsigned uVl = uVh + 64 * FLQ * 2;

    {
        const int r0 = tid >> 4;
        const int c  = (tid & 15) * 4;
        #pragma unroll
        for (int p = 0; p < 8; p++) {
            int r = r0 + p * 16;
            float4 v = *(const float4*)&Q[((size_t)(b * TT + q0 + r)) * EE + headOff + c];
            v.x *= 0.125f; v.y *= 0.125f; v.z *= 0.125f; v.w *= 0.125f;
            unsigned h01, l01, h23, l23;
            split2(v.x, v.y, h01, l01);
            split2(v.z, v.w, h23, l23);
            *(uint2*)&Qh[r * FLQ + c] = make_uint2(h01, h23);
            *(uint2*)&Ql[r * FLQ + c] = make_uint2(l01, l23);
        }
    }

    float m0 = -1e30f, m1 = -1e30f, l0 = 0.0f, l1 = 0.0f;
    float o[8][4];
    #pragma unroll
    for (int j = 0; j < 8; j++)
        #pragma unroll
        for (int e = 0; e < 4; e++) o[j][e] = 0.0f;

    const int aRow   = w * 16 + (lane & 15);
    const int aColOf = (lane >> 4) << 3;
    const int grp = lane >> 3, rr = lane & 7;
    const int bRowOf = ((grp & 2) << 2) + rr;
    const int bColOf = (grp & 1) << 3;

    for (int kv0 = 0; kv0 < TT; kv0 += 64) {
        __syncthreads();
        {
            const int r0 = tid >> 4;
            const int c  = (tid & 15) * 4;
            #pragma unroll
            for (int p = 0; p < 4; p++) {
                int r = r0 + p * 16;
                size_t gidx = ((size_t)(b * TT + kv0 + r)) * EE + headOff + c;
                float4 kv = *(const float4*)&K[gidx];
                unsigned h01, l01, h23, l23;
                split2(kv.x, kv.y, h01, l01);
                split2(kv.z, kv.w, h23, l23);
                *(uint2*)&Kh[r * FLQ + c] = make_uint2(h01, h23);
                *(uint2*)&Kl[r * FLQ + c] = make_uint2(l01, l23);

                float4 vv = *(const float4*)&V[gidx];
                float ve[4] = {vv.x, vv.y, vv.z, vv.w};
                #pragma unroll
                for (int i = 0; i < 4; i++) {
                    __nv_bfloat16 hh = __float2bfloat16(ve[i]);
                    Vh[(c + i) * FLQ + r] = hh;
                    Vl[(c + i) * FLQ + r] = __float2bfloat16(ve[i] - __bfloat162float(hh));
                }
            }
        }
        __syncthreads();

        float s[8][4];
        #pragma unroll
        for (int j = 0; j < 8; j++)
            #pragma unroll
            for (int e = 0; e < 4; e++) s[j][e] = 0.0f;

        #pragma unroll
        for (int t = 0; t < 4; t++) {
            unsigned aQh[4], aQl[4];
            unsigned aoff = (unsigned)(aRow * FLQ + t * 16 + aColOf) * 2;
            ldsm_x4(aQh, uQh + aoff);
            ldsm_x4(aQl, uQl + aoff);
            #pragma unroll
            for (int j = 0; j < 4; j++) {
                unsigned boff = (unsigned)((j * 16 + bRowOf) * FLQ + t * 16 + bColOf) * 2;
                unsigned fKh[4], fKl[4];
                ldsm_x4(fKh, uKh + boff);
                ldsm_x4(fKl, uKl + boff);
                mma16816(s[2 * j + 0], aQh, fKh + 0);
                mma16816(s[2 * j + 1], aQh, fKh + 2);
                mma16816(s[2 * j + 0], aQh, fKl + 0);
                mma16816(s[2 * j + 1], aQh, fKl + 2);
                mma16816(s[2 * j + 0], aQl, fKh + 0);
                mma16816(s[2 * j + 1], aQl, fKh + 2);
            }
        }

        float mx0 = -1e30f, mx1 = -1e30f;
        #pragma unroll
        for (int j = 0; j < 8; j++) {
            mx0 = fmaxf(mx0, fmaxf(s[j][0], s[j][1]));
            mx1 = fmaxf(mx1, fmaxf(s[j][2], s[j][3]));
        }
        mx0 = fmaxf(mx0, __shfl_xor_sync(0xffffffffu, mx0, 1));
        mx0 = fmaxf(mx0, __shfl_xor_sync(0xffffffffu, mx0, 2));
        mx1 = fmaxf(mx1, __shfl_xor_sync(0xffffffffu, mx1, 1));
        mx1 = fmaxf(mx1, __shfl_xor_sync(0xffffffffu, mx1, 2));

        float mn0 = fmaxf(m0, mx0), mn1 = fmaxf(m1, mx1);
        float c0 = fexp_neg(m0 - mn0), c1 = fexp_neg(m1 - mn1);
        m0 = mn0; m1 = mn1;

        float rs0 = 0.0f, rs1 = 0.0f;
        #pragma unroll
        for (int j = 0; j < 8; j++) {
            s[j][0] = fexp_neg(s[j][0] - mn0); rs0 += s[j][0];
            s[j][1] = fexp_neg(s[j][1] - mn0); rs0 += s[j][1];
            s[j][2] = fexp_neg(s[j][2] - mn1); rs1 += s[j][2];
            s[j][3] = fexp_neg(s[j][3] - mn1); rs1 += s[j][3];
        }
        rs0 += __shfl_xor_sync(0xffffffffu, rs0, 1);
        rs0 += __shfl_xor_sync(0xffffffffu, rs0, 2);
        rs1 += __shfl_xor_sync(0xffffffffu, rs1, 1);
        rs1 += __shfl_xor_sync(0xffffffffu, rs1, 2);
        l0 = fmaf(l0, c0, rs0);
        l1 = fmaf(l1, c1, rs1);

        #pragma unroll
        for (int j = 0; j < 8; j++) {
            o[j][0] *= c0; o[j][1] *= c0;
            o[j][2] *= c1; o[j][3] *= c1;
        }

        #pragma unroll
        for (int t = 0; t < 4; t++) {
            unsigned aPh[4], aPl[4];
            split2(s[2 * t][0],     s[2 * t][1],     aPh[0], aPl[0]);
            split2(s[2 * t][2],     s[2 * t][3],     aPh[1], aPl[1]);
            split2(s[2 * t + 1][0], s[2 * t + 1][1], aPh[2], aPl[2]);
            split2(s[2 * t + 1][2], s[2 * t + 1][3], aPh[3], aPl[3]);
            #pragma unroll
            for (int n = 0; n < 4; n++) {
                unsigned boff = (unsigned)((n * 16 + bRowOf) * FLQ + t * 16 + bColOf) * 2;
                unsigned fVh[4], fVl[4];
                ldsm_x4(fVh, uVh + boff);
                ldsm_x4(fVl, uVl + boff);
                mma16816(o[2 * n + 0], aPh, fVh + 0);
                mma16816(o[2 * n + 1], aPh, fVh + 2);
                mma16816(o[2 * n + 0], aPh, fVl + 0);
                mma16816(o[2 * n + 1], aPh, fVl + 2);
                mma16816(o[2 * n + 0], aPl, fVh + 0);
                mma16816(o[2 * n + 1], aPl, fVh + 2);
            }
        }
    }

    float inv0 = 1.0f / l0, inv1 = 1.0f / l1;
    int row0 = b * TT + q0 + w * 16 + (lane >> 2);
    #pragma unroll
    for (int j = 0; j < 8; j++) {
        size_t col = headOff + j * 8 + (lane & 3) * 2;
        unsigned h0, l0u, h1, l1u;
        split2(o[j][0] * inv0, o[j][1] * inv0, h0, l0u);
        split2(o[j][2] * inv1, o[j][3] * inv1, h1, l1u);
        *(unsigned*)&Ohi[(size_t)row0 * EE + col]       = h0;
        *(unsigned*)&Olo[(size_t)row0 * EE + col]       = l0u;
        *(unsigned*)&Ohi[(size_t)(row0 + 8) * EE + col] = h1;
        *(unsigned*)&Olo[(size_t)(row0 + 8) * EE + col] = l1u;
    }
}

// ---------------------------------------------------------------------------
// Launch
// ---------------------------------------------------------------------------
extern "C" void kernel_launch(void* const* d_in, const int* in_sizes, int n_in,
                              void* d_out, int out_size)
{
    const float* xq  = (const float*)d_in[0];
    const float* xkv = (const float*)d_in[1];
    const float* W[4] = { (const float*)d_in[2], (const float*)d_in[3],
                          (const float*)d_in[4], (const float*)d_in[5] };
    const float* qg  = (const float*)d_in[6];
    const float* qb  = (const float*)d_in[7];
    const float* kg  = (const float*)d_in[8];
    const float* kb  = (const float*)d_in[9];

    float *q, *k, *v;
    __nv_bfloat16 *ahi, *alo, *kvhi, *kvlo, *whi, *wlo;
    cudaGetSymbolAddress((void**)&q,    g_q);
    cudaGetSymbolAddress((void**)&k,    g_k);
    cudaGetSymbolAddress((void**)&v,    g_v);
    cudaGetSymbolAddress((void**)&ahi,  g_ahi);
    cudaGetSymbolAddress((void**)&alo,  g_alo);
    cudaGetSymbolAddress((void**)&kvhi, g_kvhi);
    cudaGetSymbolAddress((void**)&kvlo, g_kvlo);
    cudaGetSymbolAddress((void**)&whi,  g_whi);
    cudaGetSymbolAddress((void**)&wlo,  g_wlo);

    const size_t wsz = (size_t)EE * EE;
    const int nW4 = (int)(wsz / 4);
    const int nA4 = (int)((size_t)MROWS * EE / 4);

    int smemFlash = (2 * 128 + 4 * 64) * FLQ * 2;    // 73728 B
    cudaFuncSetAttribute((const void*)gemm_bf16x3,
                         cudaFuncAttributeMaxDynamicSharedMemorySize, GSMEM3);
    cudaFuncSetAttribute((const void*)flash_tc,
                         cudaFuncAttributeMaxDynamicSharedMemorySize, smemFlash);

    for (int i = 0; i < 4; i++)
        split_bf16<<<(nW4 + 255) / 256, 256>>>(W[i], whi + i * wsz, wlo + i * wsz, nW4);

    split_bf16<<<(nA4 + 255) / 256, 256>>>(xq,  ahi,  alo,  nA4);
    split_bf16<<<(nA4 + 255) / 256, 256>>>(xkv, kvhi, kvlo, nA4);

    // fused Q/K/V projections: z=0 -> xq*Wq -> q; z=1 -> xkv*Wk -> k; z=2 -> xkv*Wv -> v
    dim3 pGrid(EE / BN3, MROWS / BM3, 3);   // (8, 64, 3) = 1536 CTAs
    gemm_bf16x3<<<pGrid, 256, GSMEM3>>>(ahi, alo, kvhi, kvlo, whi, wlo,
                                        q, k, v, 0, MROWS, EE, EE);

    ln_rows<<<MROWS, 256>>>(q, qg, qb);
    ln_rows<<<MROWS, 256>>>(k, kg, kb);

    // flash writes the context pre-split into ahi/alo (xq split is dead now)
    flash_tc<<<dim3(TT / 128, HH, BBATCH), 256, smemFlash>>>(q, k, v, ahi, alo);

    // O projection: single-z launch, weight slab 3, output -> d_out
    dim3 oGrid(EE / BN3, MROWS / BM3, 1);
    gemm_bf16x3<<<oGrid, 256, GSMEM3>>>(ahi, alo, ahi, alo, whi, wlo,
                                        (float*)d_out, nullptr, nullptr,
                                        3, MROWS, EE, EE);
}